// round 2
// baseline (speedup 1.0000x reference)
#include <cuda_runtime.h>
#include <math.h>

#define B_   8
#define S_   56
#define C_   192
#define L_   3136
#define SO_  28
#define L2_  784
#define H_   3
#define D_   64

// ---------------- scratch (no allocs allowed) ----------------
__device__ float g_hq[B_*L_*C_];
__device__ float g_hk[B_*L2_*C_];
__device__ float g_hv[B_*L2_*C_];
__device__ float g_q [B_*L_*C_];
__device__ float g_k [B_*L2_*C_];
__device__ float g_v [B_*L2_*C_];

// ---------------- depthwise 3x3 stride-1 + BN (q path) ----------------
// SAME pad stride1: pad_lo = pad_hi = 1
__global__ void dwq_kernel(const float* __restrict__ x,
                           const float* __restrict__ dw,
                           const float* __restrict__ sc,
                           const float* __restrict__ bi,
                           const float* __restrict__ mu,
                           const float* __restrict__ va)
{
    int b = blockIdx.y, p = blockIdx.x;
    int y = p / S_, xx = p - y * S_;
    int c = threadIdx.x;
    const float* xb = x + (size_t)b * L_ * C_ + c;
    float s = 0.f;
    #pragma unroll
    for (int dy = 0; dy < 3; dy++) {
        int iy = y + dy - 1;
        if ((unsigned)iy >= (unsigned)S_) continue;
        #pragma unroll
        for (int dx = 0; dx < 3; dx++) {
            int ix = xx + dx - 1;
            if ((unsigned)ix >= (unsigned)S_) continue;
            s += xb[(size_t)(iy * S_ + ix) * C_] * dw[(dy * 3 + dx) * C_ + c];
        }
    }
    float a = sc[c] * rsqrtf(va[c] + 1e-5f);
    g_hq[((size_t)b * L_ + p) * C_ + c] = (s - mu[c]) * a + bi[c];
}

// ---------------- depthwise 3x3 stride-2 + BN (k and v fused) ----------------
// JAX SAME, stride2, 56->28: pad_total=1 -> pad_lo=0, pad_hi=1  (iy = 2*y+dy)
__global__ void dwkv_kernel(const float* __restrict__ x,
                            const float* __restrict__ kdw,
                            const float* __restrict__ ksc,
                            const float* __restrict__ kbi,
                            const float* __restrict__ kmu,
                            const float* __restrict__ kva,
                            const float* __restrict__ vdw,
                            const float* __restrict__ vsc,
                            const float* __restrict__ vbi,
                            const float* __restrict__ vmu,
                            const float* __restrict__ vva)
{
    int b = blockIdx.y, p = blockIdx.x;
    int y = p / SO_, xx = p - y * SO_;
    int c = threadIdx.x;
    const float* xb = x + (size_t)b * L_ * C_ + c;
    float sk = 0.f, sv = 0.f;
    #pragma unroll
    for (int dy = 0; dy < 3; dy++) {
        int iy = 2 * y + dy;
        if (iy >= S_) continue;
        #pragma unroll
        for (int dx = 0; dx < 3; dx++) {
            int ix = 2 * xx + dx;
            if (ix >= S_) continue;
            float xv = xb[(size_t)(iy * S_ + ix) * C_];
            sk += xv * kdw[(dy * 3 + dx) * C_ + c];
            sv += xv * vdw[(dy * 3 + dx) * C_ + c];
        }
    }
    float ak = ksc[c] * rsqrtf(kva[c] + 1e-5f);
    float av = vsc[c] * rsqrtf(vva[c] + 1e-5f);
    g_hk[((size_t)b * L2_ + p) * C_ + c] = (sk - kmu[c]) * ak + kbi[c];
    g_hv[((size_t)b * L2_ + p) * C_ + c] = (sv - vmu[c]) * av + vbi[c];
}

// ---------------- pointwise 1x1 conv: C = A[M,192] x W[192,192] ----------------
// which: 0 -> (g_hq -> g_q), 1 -> (g_hk -> g_k), 2 -> (g_hv -> g_v)
// BM=BN=64, BK=16, 256 threads, 4x4 micro-tile. M is a multiple of 64.
__global__ void __launch_bounds__(256) pw_gemm(const float* __restrict__ W,
                                               int which, float oscale)
{
    const float* A;
    float* Cp;
    if (which == 0)      { A = g_hq; Cp = g_q; }
    else if (which == 1) { A = g_hk; Cp = g_k; }
    else                 { A = g_hv; Cp = g_v; }

    __shared__ float As[16][68];
    __shared__ float Bs[16][68];

    int tx = threadIdx.x, ty = threadIdx.y;
    int tid = ty * 16 + tx;
    int m0 = blockIdx.x * 64, n0 = blockIdx.y * 64;

    float acc[4][4];
    #pragma unroll
    for (int i = 0; i < 4; i++)
        #pragma unroll
        for (int j = 0; j < 4; j++) acc[i][j] = 0.f;

    for (int k0 = 0; k0 < C_; k0 += 16) {
        int ka = tid & 15, ma = tid >> 4;
        #pragma unroll
        for (int q = 0; q < 4; q++)
            As[ka][ma + 16 * q] = A[(size_t)(m0 + ma + 16 * q) * C_ + k0 + ka];
        int nb = tid & 63, kb = tid >> 6;
        #pragma unroll
        for (int q = 0; q < 4; q++)
            Bs[kb + 4 * q][nb] = W[(size_t)(k0 + kb + 4 * q) * C_ + n0 + nb];
        __syncthreads();
        #pragma unroll
        for (int kk = 0; kk < 16; kk++) {
            float4 a4 = *(const float4*)&As[kk][ty * 4];
            float4 b4 = *(const float4*)&Bs[kk][tx * 4];
            float av[4] = {a4.x, a4.y, a4.z, a4.w};
            float bv[4] = {b4.x, b4.y, b4.z, b4.w};
            #pragma unroll
            for (int i = 0; i < 4; i++)
                #pragma unroll
                for (int j = 0; j < 4; j++) acc[i][j] += av[i] * bv[j];
        }
        __syncthreads();
    }
    #pragma unroll
    for (int i = 0; i < 4; i++) {
        float4 o = make_float4(acc[i][0] * oscale, acc[i][1] * oscale,
                               acc[i][2] * oscale, acc[i][3] * oscale);
        *(float4*)&Cp[(size_t)(m0 + ty * 4 + i) * C_ + n0 + tx * 4] = o;
    }
}

// ---------------- flash attention, fp32 ----------------
// Per (b,h): Q[3136,64], K[784,64], V[784,64]. Q tile 128 rows, K tile 64.
// 256 threads (16x16), thread micro-tile: 8 rows x 4 cols.
#define QT   128
#define KT   64
#define QPAD 132
#define KPAD 68
#define ATTN_SMEM ((64*QPAD + 64*KPAD + 64*KPAD + 64*QPAD) * 4)

__global__ void __launch_bounds__(256) attn_kernel(float* __restrict__ out)
{
    extern __shared__ float sm[];
    float* Qt = sm;                       // [64 d][QPAD]  d-major
    float* Kt = Qt + 64 * QPAD;           // [64 d][KPAD]  d-major
    float* Vs = Kt + 64 * KPAD;           // [64 j][KPAD]  j-major
    float* Ps = Vs + 64 * KPAD;           // [64 j][QPAD]  j-major

    int tx = threadIdx.x, ty = threadIdx.y;
    int tid = ty * 16 + tx;
    int q0 = blockIdx.x * QT;
    int h = blockIdx.y, b = blockIdx.z;

    const float* qp = g_q + (size_t)b * L_ * C_ + h * D_;
    const float* kp = g_k + (size_t)b * L2_ * C_ + h * D_;
    const float* vp = g_v + (size_t)b * L2_ * C_ + h * D_;

    // load Q tile (transposed to d-major)
    {
        int d = tid & 63, r4 = tid >> 6;
        #pragma unroll
        for (int rr = 0; rr < QT / 4; rr++) {
            int r = rr * 4 + r4;
            float v = 0.f;
            if (q0 + r < L_) v = qp[(size_t)(q0 + r) * C_ + d];
            Qt[d * QPAD + r] = v;
        }
    }

    float m_i[8], l_i[8], O[8][4];
    #pragma unroll
    for (int i = 0; i < 8; i++) {
        m_i[i] = -1e30f; l_i[i] = 0.f;
        #pragma unroll
        for (int j = 0; j < 4; j++) O[i][j] = 0.f;
    }

    const int NKT = (L2_ + KT - 1) / KT;  // 13
    for (int kt = 0; kt < NKT; kt++) {
        int j0 = kt * KT;
        __syncthreads();  // previous-iter readers done; Q store visible (iter 0)
        {
            int d = tid & 63, j4 = tid >> 6;
            #pragma unroll
            for (int jj = 0; jj < KT / 4; jj++) {
                int j = jj * 4 + j4;
                int jg = j0 + j;
                float vk = 0.f, vv = 0.f;
                if (jg < L2_) {
                    vk = kp[(size_t)jg * C_ + d];
                    vv = vp[(size_t)jg * C_ + d];
                }
                Kt[d * KPAD + j] = vk;
                Vs[j * KPAD + d] = vv;
            }
        }
        __syncthreads();

        // S = Q K^T  (rows ty*8..+7, cols tx*4..+3)
        float Sv[8][4];
        #pragma unroll
        for (int i = 0; i < 8; i++)
            #pragma unroll
            for (int j = 0; j < 4; j++) Sv[i][j] = 0.f;
        #pragma unroll 4
        for (int d = 0; d < 64; d++) {
            float4 qa = *(const float4*)&Qt[d * QPAD + ty * 8];
            float4 qb = *(const float4*)&Qt[d * QPAD + ty * 8 + 4];
            float4 kv = *(const float4*)&Kt[d * KPAD + tx * 4];
            float qv[8] = {qa.x, qa.y, qa.z, qa.w, qb.x, qb.y, qb.z, qb.w};
            float kr[4] = {kv.x, kv.y, kv.z, kv.w};
            #pragma unroll
            for (int i = 0; i < 8; i++)
                #pragma unroll
                for (int j = 0; j < 4; j++) Sv[i][j] += qv[i] * kr[j];
        }
        // mask out-of-range keys (last tile)
        #pragma unroll
        for (int j = 0; j < 4; j++) {
            if (j0 + tx * 4 + j >= L2_) {
                #pragma unroll
                for (int i = 0; i < 8; i++) Sv[i][j] = -1e30f;
            }
        }
        // online softmax: reduce over the 16 tx lanes (lane bits 0..3)
        #pragma unroll
        for (int i = 0; i < 8; i++) {
            float mx = fmaxf(fmaxf(Sv[i][0], Sv[i][1]), fmaxf(Sv[i][2], Sv[i][3]));
            #pragma unroll
            for (int o = 1; o < 16; o <<= 1)
                mx = fmaxf(mx, __shfl_xor_sync(0xffffffffu, mx, o));
            float mn = fmaxf(m_i[i], mx);
            float alpha = __expf(m_i[i] - mn);
            m_i[i] = mn;
            float rs = 0.f;
            #pragma unroll
            for (int j = 0; j < 4; j++) {
                float pv = __expf(Sv[i][j] - mn);
                Sv[i][j] = pv;
                rs += pv;
            }
            #pragma unroll
            for (int o = 1; o < 16; o <<= 1)
                rs += __shfl_xor_sync(0xffffffffu, rs, o);
            l_i[i] = l_i[i] * alpha + rs;
            #pragma unroll
            for (int j = 0; j < 4; j++) O[i][j] *= alpha;
            #pragma unroll
            for (int j = 0; j < 4; j++)
                Ps[(tx * 4 + j) * QPAD + ty * 8 + i] = Sv[i][j];
        }
        __syncthreads();

        // O += P V   (rows ty*8..+7, out-dims tx*4..+3)
        #pragma unroll 4
        for (int j = 0; j < KT; j++) {
            float4 pa = *(const float4*)&Ps[j * QPAD + ty * 8];
            float4 pb = *(const float4*)&Ps[j * QPAD + ty * 8 + 4];
            float4 vv = *(const float4*)&Vs[j * KPAD + tx * 4];
            float pv[8] = {pa.x, pa.y, pa.z, pa.w, pb.x, pb.y, pb.z, pb.w};
            float vr[4] = {vv.x, vv.y, vv.z, vv.w};
            #pragma unroll
            for (int i = 0; i < 8; i++)
                #pragma unroll
                for (int j2 = 0; j2 < 4; j2++) O[i][j2] += pv[i] * vr[j2];
        }
    }

    #pragma unroll
    for (int i = 0; i < 8; i++) {
        int r = q0 + ty * 8 + i;
        if (r >= L_) continue;
        float inv = 1.f / l_i[i];
        float4 o = make_float4(O[i][0] * inv, O[i][1] * inv,
                               O[i][2] * inv, O[i][3] * inv);
        *(float4*)&out[((size_t)b * L_ + r) * C_ + h * D_ + tx * 4] = o;
    }
}

// ---------------- launch ----------------
extern "C" void kernel_launch(void* const* d_in, const int* in_sizes, int n_in,
                              void* d_out, int out_size)
{
    const float* x       = (const float*)d_in[0];
    const float* q_dw    = (const float*)d_in[1];
    const float* q_scale = (const float*)d_in[2];
    const float* q_bias  = (const float*)d_in[3];
    const float* q_mean  = (const float*)d_in[4];
    const float* q_var   = (const float*)d_in[5];
    const float* q_pw    = (const float*)d_in[6];
    const float* k_dw    = (const float*)d_in[7];
    const float* k_scale = (const float*)d_in[8];
    const float* k_bias  = (const float*)d_in[9];
    const float* k_mean  = (const float*)d_in[10];
    const float* k_var   = (const float*)d_in[11];
    const float* k_pw    = (const float*)d_in[12];
    const float* v_dw    = (const float*)d_in[13];
    const float* v_scale = (const float*)d_in[14];
    const float* v_bias  = (const float*)d_in[15];
    const float* v_mean  = (const float*)d_in[16];
    const float* v_var   = (const float*)d_in[17];
    const float* v_pw    = (const float*)d_in[18];
    float* out = (float*)d_out;

    cudaFuncSetAttribute(attn_kernel,
                         cudaFuncAttributeMaxDynamicSharedMemorySize, ATTN_SMEM);

    dwq_kernel<<<dim3(L_, B_), C_>>>(x, q_dw, q_scale, q_bias, q_mean, q_var);
    dwkv_kernel<<<dim3(L2_, B_), C_>>>(x,
        k_dw, k_scale, k_bias, k_mean, k_var,
        v_dw, v_scale, v_bias, v_mean, v_var);

    pw_gemm<<<dim3((B_ * L_) / 64, C_ / 64), dim3(16, 16)>>>(q_pw, 0, 0.125f);
    pw_gemm<<<dim3((B_ * L2_) / 64, C_ / 64), dim3(16, 16)>>>(k_pw, 1, 1.0f);
    pw_gemm<<<dim3((B_ * L2_) / 64, C_ / 64), dim3(16, 16)>>>(v_pw, 2, 1.0f);

    attn_kernel<<<dim3((L_ + QT - 1) / QT, H_, B_), dim3(16, 16), ATTN_SMEM>>>(out);
}

// round 3
// speedup vs baseline: 2.2087x; 2.2087x over previous
#include <cuda_runtime.h>
#include <math.h>
#include <stdint.h>

#define B_   8
#define S_   56
#define C_   192
#define L_   3136
#define SO_  28
#define L2_  784
#define H_   3
#define D_   64

// ---------------- scratch (no allocs allowed) ----------------
__device__ float g_hq[B_*L_*C_];
__device__ float g_hk[B_*L2_*C_];
__device__ float g_hv[B_*L2_*C_];
__device__ float g_q [B_*L_*C_];
__device__ float g_k [B_*L2_*C_];
__device__ float g_v [B_*L2_*C_];

// ---------------- helpers ----------------
__device__ __forceinline__ float to_tf32(float x) {
    float r;
    asm("cvt.rna.tf32.f32 %0, %1;" : "=f"(r) : "f"(x));
    return r;
}
__device__ __forceinline__ void cp16(void* dst, const void* src) {
    uint32_t d = (uint32_t)__cvta_generic_to_shared(dst);
    asm volatile("cp.async.cg.shared.global [%0], [%1], 16;" :: "r"(d), "l"(src));
}
#define CP_COMMIT()  asm volatile("cp.async.commit_group;")
#define CP_WAIT1()   asm volatile("cp.async.wait_group 1;")

// D += A(16x8) * B(8x8), tf32, fp32 accum
__device__ __forceinline__ void mma8(float* c,
                                     uint32_t a0, uint32_t a1, uint32_t a2, uint32_t a3,
                                     uint32_t b0, uint32_t b1) {
    asm volatile("mma.sync.aligned.m16n8k8.row.col.f32.tf32.tf32.f32 "
                 "{%0,%1,%2,%3}, {%4,%5,%6,%7}, {%8,%9}, {%0,%1,%2,%3};"
                 : "+f"(c[0]), "+f"(c[1]), "+f"(c[2]), "+f"(c[3])
                 : "r"(a0), "r"(a1), "r"(a2), "r"(a3), "r"(b0), "r"(b1));
}

// ---------------- depthwise 3x3 stride-1 + BN (q path) ----------------
__global__ void dwq_kernel(const float* __restrict__ x,
                           const float* __restrict__ dw,
                           const float* __restrict__ sc,
                           const float* __restrict__ bi,
                           const float* __restrict__ mu,
                           const float* __restrict__ va)
{
    int b = blockIdx.y, p = blockIdx.x;
    int y = p / S_, xx = p - y * S_;
    int c = threadIdx.x;
    const float* xb = x + (size_t)b * L_ * C_ + c;
    float s = 0.f;
    #pragma unroll
    for (int dy = 0; dy < 3; dy++) {
        int iy = y + dy - 1;
        if ((unsigned)iy >= (unsigned)S_) continue;
        #pragma unroll
        for (int dx = 0; dx < 3; dx++) {
            int ix = xx + dx - 1;
            if ((unsigned)ix >= (unsigned)S_) continue;
            s += xb[(size_t)(iy * S_ + ix) * C_] * dw[(dy * 3 + dx) * C_ + c];
        }
    }
    float a = sc[c] * rsqrtf(va[c] + 1e-5f);
    g_hq[((size_t)b * L_ + p) * C_ + c] = to_tf32((s - mu[c]) * a + bi[c]);
}

// ---------------- depthwise 3x3 stride-2 + BN (k and v fused) ----------------
// JAX SAME stride2 56->28: pad_lo=0, pad_hi=1 (iy = 2*y+dy)
__global__ void dwkv_kernel(const float* __restrict__ x,
                            const float* __restrict__ kdw,
                            const float* __restrict__ ksc,
                            const float* __restrict__ kbi,
                            const float* __restrict__ kmu,
                            const float* __restrict__ kva,
                            const float* __restrict__ vdw,
                            const float* __restrict__ vsc,
                            const float* __restrict__ vbi,
                            const float* __restrict__ vmu,
                            const float* __restrict__ vva)
{
    int b = blockIdx.y, p = blockIdx.x;
    int y = p / SO_, xx = p - y * SO_;
    int c = threadIdx.x;
    const float* xb = x + (size_t)b * L_ * C_ + c;
    float sk = 0.f, sv = 0.f;
    #pragma unroll
    for (int dy = 0; dy < 3; dy++) {
        int iy = 2 * y + dy;
        if (iy >= S_) continue;
        #pragma unroll
        for (int dx = 0; dx < 3; dx++) {
            int ix = 2 * xx + dx;
            if (ix >= S_) continue;
            float xv = xb[(size_t)(iy * S_ + ix) * C_];
            sk += xv * kdw[(dy * 3 + dx) * C_ + c];
            sv += xv * vdw[(dy * 3 + dx) * C_ + c];
        }
    }
    float ak = ksc[c] * rsqrtf(kva[c] + 1e-5f);
    float av = vsc[c] * rsqrtf(vva[c] + 1e-5f);
    g_hk[((size_t)b * L2_ + p) * C_ + c] = to_tf32((sk - kmu[c]) * ak + kbi[c]);
    g_hv[((size_t)b * L2_ + p) * C_ + c] = to_tf32((sv - vmu[c]) * av + vbi[c]);
}

// ---------------- pointwise 1x1 conv via tf32 mma ----------------
// C[M,192] = A[M,192] x W[192,192]; CTA tile 128x64, warp tile 16x64.
// which: 0 -> (g_hq -> g_q), 1 -> (g_hk -> g_k), 2 -> (g_hv -> g_v)
// smem: As double-buffered [2][128][20] + Bs full panel [192][72]
#define PW_SMEM ((2*128*20 + 192*72) * 4)
__global__ void __launch_bounds__(256) pw_mma(const float* __restrict__ W,
                                              int which, float oscale)
{
    const float* A;
    float* Cp;
    if (which == 0)      { A = g_hq; Cp = g_q; }
    else if (which == 1) { A = g_hk; Cp = g_k; }
    else                 { A = g_hv; Cp = g_v; }

    extern __shared__ float sm[];
    float* As = sm;            // 2 * 128*20
    float* Bs = sm + 2*128*20; // 192*72

    const int tid = threadIdx.x;
    const int w = tid >> 5, lane = tid & 31;
    const int g = lane >> 2, tg = lane & 3;
    const int m0 = blockIdx.x * 128, n0 = blockIdx.y * 64;

    // issue A tile 0
    #pragma unroll
    for (int p = 0; p < 2; p++) {
        int id = tid + p * 256;
        int r = id >> 2, c = (id & 3) << 2;
        cp16(&As[r * 20 + c], A + (size_t)(m0 + r) * C_ + c);
    }
    CP_COMMIT();

    // stage full B panel (convert to tf32)
    #pragma unroll 4
    for (int idx = tid; idx < 192 * 64; idx += 256) {
        int k = idx >> 6, n = idx & 63;
        Bs[k * 72 + n] = to_tf32(W[(size_t)k * C_ + n0 + n]);
    }

    float Cv[8][4];
    #pragma unroll
    for (int i = 0; i < 8; i++)
        #pragma unroll
        for (int j = 0; j < 4; j++) Cv[i][j] = 0.f;

    const int r0 = 16 * w + g;
    for (int i = 0; i < 12; i++) {
        __syncthreads();   // prev compute done (buffer free); Bs visible (i==0)
        int kn = (i + 1 < 12) ? (i + 1) * 16 : 0;
        float* Ab = As + ((i + 1) & 1) * 2560;
        #pragma unroll
        for (int p = 0; p < 2; p++) {
            int id = tid + p * 256;
            int r = id >> 2, c = (id & 3) << 2;
            cp16(&Ab[r * 20 + c], A + (size_t)(m0 + r) * C_ + kn + c);
        }
        CP_COMMIT();
        CP_WAIT1();
        __syncthreads();

        const uint32_t* Au = (const uint32_t*)(As + (i & 1) * 2560);
        const uint32_t* Bu = (const uint32_t*)Bs;
        #pragma unroll
        for (int ks = 0; ks < 2; ks++) {
            uint32_t a0 = Au[r0 * 20 + ks * 8 + tg];
            uint32_t a1 = Au[(r0 + 8) * 20 + ks * 8 + tg];
            uint32_t a2 = Au[r0 * 20 + ks * 8 + tg + 4];
            uint32_t a3 = Au[(r0 + 8) * 20 + ks * 8 + tg + 4];
            int kb = i * 16 + ks * 8;
            #pragma unroll
            for (int nf = 0; nf < 8; nf++) {
                uint32_t b0 = Bu[(kb + tg) * 72 + nf * 8 + g];
                uint32_t b1 = Bu[(kb + tg + 4) * 72 + nf * 8 + g];
                mma8(Cv[nf], a0, a1, a2, a3, b0, b1);
            }
        }
    }

    // epilogue: scale, round to tf32 (consumed by tf32 mma downstream), store
    float* o0 = Cp + (size_t)(m0 + r0) * C_ + n0;
    float* o1 = o0 + (size_t)8 * C_;
    #pragma unroll
    for (int nf = 0; nf < 8; nf++) {
        float2 u0 = make_float2(to_tf32(Cv[nf][0] * oscale), to_tf32(Cv[nf][1] * oscale));
        float2 u1 = make_float2(to_tf32(Cv[nf][2] * oscale), to_tf32(Cv[nf][3] * oscale));
        *(float2*)&o0[nf * 8 + 2 * tg] = u0;
        *(float2*)&o1[nf * 8 + 2 * tg] = u1;
    }
}

// ---------------- flash attention via tf32 mma ----------------
// CTA: 128 q-rows, 8 warps x 16 rows. K-tile 64, double-buffered cp.async.
// Q fragments register-resident. P via per-warp smem (overlays Q staging).
#define NKT 13
#define ATTN_SMEM ((128*68 + 2*64*68 + 2*64*68) * 4)
__global__ void __launch_bounds__(256) attn_mma(float* __restrict__ out)
{
    extern __shared__ float sm[];
    float* QP = sm;                  // 128*68 : Q staging, then per-warp P
    float* KS = sm + 128*68;         // 2 x 64*68
    float* VS = sm + 128*68 + 2*64*68;

    const int tid = threadIdx.x;
    const int w = tid >> 5, lane = tid & 31;
    const int g = lane >> 2, tg = lane & 3;
    const int q0 = blockIdx.x * 128;
    const int h = blockIdx.y, b = blockIdx.z;

    const float* qp = g_q + (size_t)b * L_ * C_ + h * D_;
    const float* kp = g_k + (size_t)b * L2_ * C_ + h * D_;
    const float* vp = g_v + (size_t)b * L2_ * C_ + h * D_;

    // prologue: Q tile (group 0)
    #pragma unroll
    for (int p = 0; p < 8; p++) {
        int id = tid + p * 256;
        int r = id >> 4, c = (id & 15) << 2;
        int rg = q0 + r; if (rg > L_ - 1) rg = L_ - 1;
        cp16(&QP[r * 68 + c], qp + (size_t)rg * C_ + c);
    }
    CP_COMMIT();
    // KV tile 0 (group 1)
    #pragma unroll
    for (int p = 0; p < 4; p++) {
        int id = tid + p * 256;
        int j = id >> 4, c = (id & 15) << 2;
        cp16(&KS[j * 68 + c], kp + (size_t)j * C_ + c);
        cp16(&VS[j * 68 + c], vp + (size_t)j * C_ + c);
    }
    CP_COMMIT();
    CP_WAIT1();          // Q done
    __syncthreads();

    // Q fragments: 16 rows x 64 cols per warp -> 32 regs
    uint32_t Qa[8][4];
    {
        const uint32_t* Qu = (const uint32_t*)QP;
        int r0 = 16 * w + g;
        #pragma unroll
        for (int ks = 0; ks < 8; ks++) {
            Qa[ks][0] = Qu[r0 * 68 + ks * 8 + tg];
            Qa[ks][1] = Qu[(r0 + 8) * 68 + ks * 8 + tg];
            Qa[ks][2] = Qu[r0 * 68 + ks * 8 + tg + 4];
            Qa[ks][3] = Qu[(r0 + 8) * 68 + ks * 8 + tg + 4];
        }
    }

    float Ov[8][4];
    #pragma unroll
    for (int i = 0; i < 8; i++)
        #pragma unroll
        for (int j = 0; j < 4; j++) Ov[i][j] = 0.f;
    float m0 = -1e30f, m1 = -1e30f, l0 = 0.f, l1 = 0.f;

    float* Pw = QP + w * 16 * 68;    // warp-private P region (16 x 68)

    for (int kt = 0; kt < NKT; kt++) {
        __syncthreads();             // prev compute done; Qa loads done (kt==0)
        {   // issue next KV tile into the other buffer
            int nk = (kt + 1 < NKT) ? kt + 1 : 0;
            int nb = (kt + 1) & 1;
            float* Kb = KS + nb * (64 * 68);
            float* Vb = VS + nb * (64 * 68);
            int j0n = nk * 64;
            #pragma unroll
            for (int p = 0; p < 4; p++) {
                int id = tid + p * 256;
                int j = id >> 4, c = (id & 15) << 2;
                int jg = j0n + j; if (jg > L2_ - 1) jg = L2_ - 1;
                cp16(&Kb[j * 68 + c], kp + (size_t)jg * C_ + c);
                cp16(&Vb[j * 68 + c], vp + (size_t)jg * C_ + c);
            }
        }
        CP_COMMIT();
        CP_WAIT1();                  // current tile ready
        __syncthreads();

        const uint32_t* Ku = (const uint32_t*)(KS + (kt & 1) * (64 * 68));
        const uint32_t* Vu = (const uint32_t*)(VS + (kt & 1) * (64 * 68));

        // S = Q K^T  : warp 16 x 64
        float Sc[8][4];
        #pragma unroll
        for (int i = 0; i < 8; i++)
            #pragma unroll
            for (int j = 0; j < 4; j++) Sc[i][j] = 0.f;
        #pragma unroll
        for (int ks = 0; ks < 8; ks++) {
            #pragma unroll
            for (int nf = 0; nf < 8; nf++) {
                uint32_t b0 = Ku[(nf * 8 + g) * 68 + ks * 8 + tg];
                uint32_t b1 = Ku[(nf * 8 + g) * 68 + ks * 8 + tg + 4];
                mma8(Sc[nf], Qa[ks][0], Qa[ks][1], Qa[ks][2], Qa[ks][3], b0, b1);
            }
        }

        int j0 = kt * 64;
        if (j0 + 64 > L2_) {         // last tile: mask invalid keys
            #pragma unroll
            for (int nf = 0; nf < 8; nf++) {
                int c0 = j0 + nf * 8 + 2 * tg;
                if (c0 >= L2_)     { Sc[nf][0] = -1e30f; Sc[nf][2] = -1e30f; }
                if (c0 + 1 >= L2_) { Sc[nf][1] = -1e30f; Sc[nf][3] = -1e30f; }
            }
        }

        // online softmax (rows g and g+8; col lanes = tg quad -> xor 1,2)
        float mx0 = -1e30f, mx1 = -1e30f;
        #pragma unroll
        for (int nf = 0; nf < 8; nf++) {
            mx0 = fmaxf(mx0, fmaxf(Sc[nf][0], Sc[nf][1]));
            mx1 = fmaxf(mx1, fmaxf(Sc[nf][2], Sc[nf][3]));
        }
        mx0 = fmaxf(mx0, __shfl_xor_sync(0xffffffffu, mx0, 1));
        mx0 = fmaxf(mx0, __shfl_xor_sync(0xffffffffu, mx0, 2));
        mx1 = fmaxf(mx1, __shfl_xor_sync(0xffffffffu, mx1, 1));
        mx1 = fmaxf(mx1, __shfl_xor_sync(0xffffffffu, mx1, 2));
        float mn0 = fmaxf(m0, mx0), mn1 = fmaxf(m1, mx1);
        float al0 = __expf(m0 - mn0), al1 = __expf(m1 - mn1);
        m0 = mn0; m1 = mn1;
        float s0 = 0.f, s1 = 0.f;
        #pragma unroll
        for (int nf = 0; nf < 8; nf++) {
            float p00 = __expf(Sc[nf][0] - mn0);
            float p01 = __expf(Sc[nf][1] - mn0);
            float p10 = __expf(Sc[nf][2] - mn1);
            float p11 = __expf(Sc[nf][3] - mn1);
            s0 += p00 + p01; s1 += p10 + p11;
            Pw[g * 68 + nf * 8 + 2 * tg]           = to_tf32(p00);
            Pw[g * 68 + nf * 8 + 2 * tg + 1]       = to_tf32(p01);
            Pw[(g + 8) * 68 + nf * 8 + 2 * tg]     = to_tf32(p10);
            Pw[(g + 8) * 68 + nf * 8 + 2 * tg + 1] = to_tf32(p11);
        }
        s0 += __shfl_xor_sync(0xffffffffu, s0, 1);
        s0 += __shfl_xor_sync(0xffffffffu, s0, 2);
        s1 += __shfl_xor_sync(0xffffffffu, s1, 1);
        s1 += __shfl_xor_sync(0xffffffffu, s1, 2);
        l0 = l0 * al0 + s0;
        l1 = l1 * al1 + s1;
        #pragma unroll
        for (int df = 0; df < 8; df++) {
            Ov[df][0] *= al0; Ov[df][1] *= al0;
            Ov[df][2] *= al1; Ov[df][3] *= al1;
        }
        __syncwarp();

        // O += P V
        const uint32_t* Pu = (const uint32_t*)Pw;
        #pragma unroll
        for (int ks = 0; ks < 8; ks++) {
            uint32_t a0 = Pu[g * 68 + ks * 8 + tg];
            uint32_t a1 = Pu[(g + 8) * 68 + ks * 8 + tg];
            uint32_t a2 = Pu[g * 68 + ks * 8 + tg + 4];
            uint32_t a3 = Pu[(g + 8) * 68 + ks * 8 + tg + 4];
            #pragma unroll
            for (int df = 0; df < 8; df++) {
                uint32_t b0 = Vu[(ks * 8 + tg) * 68 + df * 8 + g];
                uint32_t b1 = Vu[(ks * 8 + tg + 4) * 68 + df * 8 + g];
                mma8(Ov[df], a0, a1, a2, a3, b0, b1);
            }
        }
    }

    // epilogue
    float i0 = 1.f / l0, i1 = 1.f / l1;
    int rg0 = q0 + 16 * w + g;
    if (rg0 < L_) {
        float* o = out + ((size_t)b * L_ + rg0) * C_ + h * D_;
        #pragma unroll
        for (int df = 0; df < 8; df++)
            *(float2*)&o[df * 8 + 2 * tg] =
                make_float2(Ov[df][0] * i0, Ov[df][1] * i0);
    }
    int rg1 = rg0 + 8;
    if (rg1 < L_) {
        float* o = out + ((size_t)b * L_ + rg1) * C_ + h * D_;
        #pragma unroll
        for (int df = 0; df < 8; df++)
            *(float2*)&o[df * 8 + 2 * tg] =
                make_float2(Ov[df][2] * i1, Ov[df][3] * i1);
    }
}

// ---------------- launch ----------------
extern "C" void kernel_launch(void* const* d_in, const int* in_sizes, int n_in,
                              void* d_out, int out_size)
{
    const float* x       = (const float*)d_in[0];
    const float* q_dw    = (const float*)d_in[1];
    const float* q_scale = (const float*)d_in[2];
    const float* q_bias  = (const float*)d_in[3];
    const float* q_mean  = (const float*)d_in[4];
    const float* q_var   = (const float*)d_in[5];
    const float* q_pw    = (const float*)d_in[6];
    const float* k_dw    = (const float*)d_in[7];
    const float* k_scale = (const float*)d_in[8];
    const float* k_bias  = (const float*)d_in[9];
    const float* k_mean  = (const float*)d_in[10];
    const float* k_var   = (const float*)d_in[11];
    const float* k_pw    = (const float*)d_in[12];
    const float* v_dw    = (const float*)d_in[13];
    const float* v_scale = (const float*)d_in[14];
    const float* v_bias  = (const float*)d_in[15];
    const float* v_mean  = (const float*)d_in[16];
    const float* v_var   = (const float*)d_in[17];
    const float* v_pw    = (const float*)d_in[18];
    float* out = (float*)d_out;

    cudaFuncSetAttribute(pw_mma,
                         cudaFuncAttributeMaxDynamicSharedMemorySize, PW_SMEM);
    cudaFuncSetAttribute(attn_mma,
                         cudaFuncAttributeMaxDynamicSharedMemorySize, ATTN_SMEM);

    dwq_kernel<<<dim3(L_, B_), C_>>>(x, q_dw, q_scale, q_bias, q_mean, q_var);
    dwkv_kernel<<<dim3(L2_, B_), C_>>>(x,
        k_dw, k_scale, k_bias, k_mean, k_var,
        v_dw, v_scale, v_bias, v_mean, v_var);

    pw_mma<<<dim3((B_ * L_) / 128, 3), 256, PW_SMEM>>>(q_pw, 0, 0.125f);
    pw_mma<<<dim3((B_ * L2_) / 128, 3), 256, PW_SMEM>>>(k_pw, 1, 1.0f);
    pw_mma<<<dim3((B_ * L2_) / 128, 3), 256, PW_SMEM>>>(v_pw, 2, 1.0f);

    attn_mma<<<dim3((L_ + 127) / 128, H_, B_), 256, ATTN_SMEM>>>(out);
}

// round 5
// speedup vs baseline: 2.3711x; 1.0735x over previous
#include <cuda_runtime.h>
#include <math.h>
#include <stdint.h>

#define B_   8
#define S_   56
#define C_   192
#define L_   3136
#define SO_  28
#define L2_  784
#define H_   3
#define D_   64

// ---------------- scratch (no allocs allowed) ----------------
__device__ float g_hq[B_*L_*C_];
__device__ float g_hk[B_*L2_*C_];
__device__ float g_hv[B_*L2_*C_];
__device__ float g_q [B_*L_*C_];
__device__ float g_k [B_*L2_*C_];
__device__ float g_v [B_*L2_*C_];

// ---------------- helpers ----------------
__device__ __forceinline__ float to_tf32(float x) {
    float r;
    asm("cvt.rna.tf32.f32 %0, %1;" : "=f"(r) : "f"(x));
    return r;
}
__device__ __forceinline__ void cp16(void* dst, const void* src) {
    uint32_t d = (uint32_t)__cvta_generic_to_shared(dst);
    asm volatile("cp.async.cg.shared.global [%0], [%1], 16;" :: "r"(d), "l"(src));
}
#define CP_COMMIT()   asm volatile("cp.async.commit_group;")
#define CP_WAIT0()    asm volatile("cp.async.wait_group 0;")
#define CP_WAIT1()    asm volatile("cp.async.wait_group 1;")
#define CP_WAIT2()    asm volatile("cp.async.wait_group 2;")

// D += A(16x8) * B(8x8), tf32, fp32 accum
__device__ __forceinline__ void mma8(float* c,
                                     uint32_t a0, uint32_t a1, uint32_t a2, uint32_t a3,
                                     uint32_t b0, uint32_t b1) {
    asm volatile("mma.sync.aligned.m16n8k8.row.col.f32.tf32.tf32.f32 "
                 "{%0,%1,%2,%3}, {%4,%5,%6,%7}, {%8,%9}, {%0,%1,%2,%3};"
                 : "+f"(c[0]), "+f"(c[1]), "+f"(c[2]), "+f"(c[3])
                 : "r"(a0), "r"(a1), "r"(a2), "r"(a3), "r"(b0), "r"(b1));
}

// ---------------- depthwise 3x3 + BN, q (stride1) and k/v (stride2) fused grid ----------------
__global__ void dw_all(const float* __restrict__ x,
                       const float* __restrict__ qdw, const float* __restrict__ qsc,
                       const float* __restrict__ qbi, const float* __restrict__ qmu,
                       const float* __restrict__ qva,
                       const float* __restrict__ kdw, const float* __restrict__ ksc,
                       const float* __restrict__ kbi, const float* __restrict__ kmu,
                       const float* __restrict__ kva,
                       const float* __restrict__ vdw, const float* __restrict__ vsc,
                       const float* __restrict__ vbi, const float* __restrict__ vmu,
                       const float* __restrict__ vva)
{
    int b = blockIdx.y, p = blockIdx.x;
    int c = threadIdx.x;
    const float* xb = x + (size_t)b * L_ * C_ + c;
    if (p < L_) {
        // stride-1 q path: pad_lo = pad_hi = 1
        int y = p / S_, xx = p - y * S_;
        float s = 0.f;
        #pragma unroll
        for (int dy = 0; dy < 3; dy++) {
            int iy = y + dy - 1;
            if ((unsigned)iy >= (unsigned)S_) continue;
            #pragma unroll
            for (int dx = 0; dx < 3; dx++) {
                int ix = xx + dx - 1;
                if ((unsigned)ix >= (unsigned)S_) continue;
                s += xb[(size_t)(iy * S_ + ix) * C_] * qdw[(dy * 3 + dx) * C_ + c];
            }
        }
        float a = qsc[c] * rsqrtf(qva[c] + 1e-5f);
        g_hq[((size_t)b * L_ + p) * C_ + c] = to_tf32((s - qmu[c]) * a + qbi[c]);
    } else {
        // stride-2 k/v path: JAX SAME 56->28: pad_lo=0, pad_hi=1 (iy = 2*y+dy)
        int p2 = p - L_;
        int y = p2 / SO_, xx = p2 - y * SO_;
        float sk = 0.f, sv = 0.f;
        #pragma unroll
        for (int dy = 0; dy < 3; dy++) {
            int iy = 2 * y + dy;
            if (iy >= S_) continue;
            #pragma unroll
            for (int dx = 0; dx < 3; dx++) {
                int ix = 2 * xx + dx;
                if (ix >= S_) continue;
                float xv = xb[(size_t)(iy * S_ + ix) * C_];
                sk += xv * kdw[(dy * 3 + dx) * C_ + c];
                sv += xv * vdw[(dy * 3 + dx) * C_ + c];
            }
        }
        float ak = ksc[c] * rsqrtf(kva[c] + 1e-5f);
        float av = vsc[c] * rsqrtf(vva[c] + 1e-5f);
        g_hk[((size_t)b * L2_ + p2) * C_ + c] = to_tf32((sk - kmu[c]) * ak + kbi[c]);
        g_hv[((size_t)b * L2_ + p2) * C_ + c] = to_tf32((sv - vmu[c]) * av + vbi[c]);
    }
}

// ---------------- pointwise 1x1 conv, all three projections, 4-stage pipeline ----------------
// grid.x: [0,196) q-tiles, [196,245) k-tiles, [245,294) v-tiles; grid.y: n-block of 64.
// CTA 128x64, 256 thr, warp tile 16x64, BK=16, 4-deep cp.async ring.
#define PW_STG  4
#define PW_SMEM ((PW_STG*128*20 + 192*72) * 4)
__global__ void __launch_bounds__(256) pw_all(const float* __restrict__ Wq,
                                              const float* __restrict__ Wk,
                                              const float* __restrict__ Wv)
{
    const float* A; const float* W; float* Cp; float oscale; int m0;
    int bx = blockIdx.x;
    if (bx < 196)      { A = g_hq; Cp = g_q; W = Wq; oscale = 0.125f; m0 = bx * 128; }
    else if (bx < 245) { A = g_hk; Cp = g_k; W = Wk; oscale = 1.0f;  m0 = (bx - 196) * 128; }
    else               { A = g_hv; Cp = g_v; W = Wv; oscale = 1.0f;  m0 = (bx - 245) * 128; }
    const int n0 = blockIdx.y * 64;

    extern __shared__ float sm[];
    float* As = sm;                 // PW_STG * 2560
    float* Bs = sm + PW_STG * 2560; // 192*72

    const int tid = threadIdx.x;
    const int w = tid >> 5, lane = tid & 31;
    const int g = lane >> 2, tg = lane & 3;

    // issue prefetch for stages 0..2
    #pragma unroll
    for (int s = 0; s < 3; s++) {
        float* Ab = As + s * 2560;
        #pragma unroll
        for (int p = 0; p < 2; p++) {
            int id = tid + p * 256;
            int r = id >> 2, c = (id & 3) << 2;
            cp16(&Ab[r * 20 + c], A + (size_t)(m0 + r) * C_ + s * 16 + c);
        }
        CP_COMMIT();
    }

    // stage full B panel (tf32-rounded)
    #pragma unroll 4
    for (int idx = tid; idx < 192 * 64; idx += 256) {
        int k = idx >> 6, n = idx & 63;
        Bs[k * 72 + n] = to_tf32(W[(size_t)k * C_ + n0 + n]);
    }

    float Cv[8][4];
    #pragma unroll
    for (int i = 0; i < 8; i++)
        #pragma unroll
        for (int j = 0; j < 4; j++) Cv[i][j] = 0.f;

    const int r0 = 16 * w + g;
    const uint32_t* Bu = (const uint32_t*)Bs;

    for (int s = 0; s < 12; s++) {
        CP_WAIT2();          // pending {s,s+1,s+2} -> stage s complete
        __syncthreads();     // all warps done with stage s-1 buffer; Bs visible (s==0)
        if (s < 9) {         // prefetch stage s+3 into ring buffer (s+3)&3
            float* Ab = As + ((s + 3) & 3) * 2560;
            #pragma unroll
            for (int p = 0; p < 2; p++) {
                int id = tid + p * 256;
                int r = id >> 2, c = (id & 3) << 2;
                cp16(&Ab[r * 20 + c], A + (size_t)(m0 + r) * C_ + (s + 3) * 16 + c);
            }
        }
        CP_COMMIT();         // commit (possibly empty) to keep group accounting uniform

        const uint32_t* Au = (const uint32_t*)(As + (s & 3) * 2560);
        #pragma unroll
        for (int ks = 0; ks < 2; ks++) {
            uint32_t a0 = Au[r0 * 20 + ks * 8 + tg];
            uint32_t a1 = Au[(r0 + 8) * 20 + ks * 8 + tg];
            uint32_t a2 = Au[r0 * 20 + ks * 8 + tg + 4];
            uint32_t a3 = Au[(r0 + 8) * 20 + ks * 8 + tg + 4];
            int kb = s * 16 + ks * 8;
            #pragma unroll
            for (int nf = 0; nf < 8; nf++) {
                uint32_t b0 = Bu[(kb + tg) * 72 + nf * 8 + g];
                uint32_t b1 = Bu[(kb + tg + 4) * 72 + nf * 8 + g];
                mma8(Cv[nf], a0, a1, a2, a3, b0, b1);
            }
        }
    }

    // epilogue: scale, round to tf32 (consumed by tf32 mma downstream), store
    float* o0 = Cp + (size_t)(m0 + r0) * C_ + n0;
    float* o1 = o0 + (size_t)8 * C_;
    #pragma unroll
    for (int nf = 0; nf < 8; nf++) {
        float2 u0 = make_float2(to_tf32(Cv[nf][0] * oscale), to_tf32(Cv[nf][1] * oscale));
        float2 u1 = make_float2(to_tf32(Cv[nf][2] * oscale), to_tf32(Cv[nf][3] * oscale));
        *(float2*)&o0[nf * 8 + 2 * tg] = u0;
        *(float2*)&o1[nf * 8 + 2 * tg] = u1;
    }
}

// ---------------- flash attention via tf32 mma, single barrier per K-tile ----------------
// CTA: 128 q-rows, 8 warps x 16 rows. K-tile 64, double-buffered cp.async,
// prefetch distance = one full tile of compute. P via per-warp smem.
#define NKT 13
#define ATTN_SMEM ((128*68 + 2*64*68 + 2*64*68) * 4)
__global__ void __launch_bounds__(256) attn_mma(float* __restrict__ out)
{
    extern __shared__ float sm[];
    float* QP = sm;                  // 128*68 : Q staging, then per-warp P
    float* KS = sm + 128*68;         // 2 x 64*68
    float* VS = sm + 128*68 + 2*64*68;

    const int tid = threadIdx.x;
    const int w = tid >> 5, lane = tid & 31;
    const int g = lane >> 2, tg = lane & 3;
    const int q0 = blockIdx.x * 128;
    const int h = blockIdx.y, b = blockIdx.z;

    const float* qp = g_q + (size_t)b * L_ * C_ + h * D_;
    const float* kp = g_k + (size_t)b * L2_ * C_ + h * D_;
    const float* vp = g_v + (size_t)b * L2_ * C_ + h * D_;

    // prologue: Q tile (group 0)
    #pragma unroll
    for (int p = 0; p < 8; p++) {
        int id = tid + p * 256;
        int r = id >> 4, c = (id & 15) << 2;
        int rg = q0 + r; if (rg > L_ - 1) rg = L_ - 1;
        cp16(&QP[r * 68 + c], qp + (size_t)rg * C_ + c);
    }
    CP_COMMIT();
    // KV tile 0 (group 1)
    #pragma unroll
    for (int p = 0; p < 4; p++) {
        int id = tid + p * 256;
        int j = id >> 4, c = (id & 15) << 2;
        cp16(&KS[j * 68 + c], kp + (size_t)j * C_ + c);
        cp16(&VS[j * 68 + c], vp + (size_t)j * C_ + c);
    }
    CP_COMMIT();
    CP_WAIT1();          // Q done (KV0 may still be in flight)
    __syncthreads();

    // Q fragments: 16 rows x 64 cols per warp -> 32 regs
    uint32_t Qa[8][4];
    {
        const uint32_t* Qu = (const uint32_t*)QP;
        int r0 = 16 * w + g;
        #pragma unroll
        for (int ks = 0; ks < 8; ks++) {
            Qa[ks][0] = Qu[r0 * 68 + ks * 8 + tg];
            Qa[ks][1] = Qu[(r0 + 8) * 68 + ks * 8 + tg];
            Qa[ks][2] = Qu[r0 * 68 + ks * 8 + tg + 4];
            Qa[ks][3] = Qu[(r0 + 8) * 68 + ks * 8 + tg + 4];
        }
    }

    float Ov[8][4];
    #pragma unroll
    for (int i = 0; i < 8; i++)
        #pragma unroll
        for (int j = 0; j < 4; j++) Ov[i][j] = 0.f;
    float m0 = -1e30f, m1 = -1e30f, l0 = 0.f, l1 = 0.f;

    float* Pw = QP + w * 16 * 68;    // warp-private P region (16 x 68)

    for (int kt = 0; kt < NKT; kt++) {
        CP_WAIT0();                  // only pending group = KV_kt -> tile ready
        __syncthreads();             // all warps done with buffer (kt+1)&1 (tile kt-1)

        if (kt + 1 < NKT) {          // prefetch next KV tile, one tile of compute ahead
            int nb = (kt + 1) & 1;
            float* Kb = KS + nb * (64 * 68);
            float* Vb = VS + nb * (64 * 68);
            int j0n = (kt + 1) * 64;
            #pragma unroll
            for (int p = 0; p < 4; p++) {
                int id = tid + p * 256;
                int j = id >> 4, c = (id & 15) << 2;
                int jg = j0n + j; if (jg > L2_ - 1) jg = L2_ - 1;
                cp16(&Kb[j * 68 + c], kp + (size_t)jg * C_ + c);
                cp16(&Vb[j * 68 + c], vp + (size_t)jg * C_ + c);
            }
            CP_COMMIT();
        }

        const uint32_t* Ku = (const uint32_t*)(KS + (kt & 1) * (64 * 68));
        const uint32_t* Vu = (const uint32_t*)(VS + (kt & 1) * (64 * 68));

        // S = Q K^T : warp 16 x 64
        float Sc[8][4];
        #pragma unroll
        for (int i = 0; i < 8; i++)
            #pragma unroll
            for (int j = 0; j < 4; j++) Sc[i][j] = 0.f;
        #pragma unroll
        for (int ks = 0; ks < 8; ks++) {
            #pragma unroll
            for (int nf = 0; nf < 8; nf++) {
                uint32_t b0 = Ku[(nf * 8 + g) * 68 + ks * 8 + tg];
                uint32_t b1 = Ku[(nf * 8 + g) * 68 + ks * 8 + tg + 4];
                mma8(Sc[nf], Qa[ks][0], Qa[ks][1], Qa[ks][2], Qa[ks][3], b0, b1);
            }
        }

        int j0 = kt * 64;
        if (j0 + 64 > L2_) {         // last tile: mask invalid keys
            #pragma unroll
            for (int nf = 0; nf < 8; nf++) {
                int c0 = j0 + nf * 8 + 2 * tg;
                if (c0 >= L2_)     { Sc[nf][0] = -1e30f; Sc[nf][2] = -1e30f; }
                if (c0 + 1 >= L2_) { Sc[nf][1] = -1e30f; Sc[nf][3] = -1e30f; }
            }
        }

        // online softmax (rows g and g+8; col reduce over quad lanes xor 1,2)
        float mx0 = -1e30f, mx1 = -1e30f;
        #pragma unroll
        for (int nf = 0; nf < 8; nf++) {
            mx0 = fmaxf(mx0, fmaxf(Sc[nf][0], Sc[nf][1]));
            mx1 = fmaxf(mx1, fmaxf(Sc[nf][2], Sc[nf][3]));
        }
        mx0 = fmaxf(mx0, __shfl_xor_sync(0xffffffffu, mx0, 1));
        mx0 = fmaxf(mx0, __shfl_xor_sync(0xffffffffu, mx0, 2));
        mx1 = fmaxf(mx1, __shfl_xor_sync(0xffffffffu, mx1, 1));
        mx1 = fmaxf(mx1, __shfl_xor_sync(0xffffffffu, mx1, 2));
        float mn0 = fmaxf(m0, mx0), mn1 = fmaxf(m1, mx1);
        float al0 = __expf(m0 - mn0), al1 = __expf(m1 - mn1);
        m0 = mn0; m1 = mn1;
        float s0 = 0.f, s1 = 0.f;
        #pragma unroll
        for (int nf = 0; nf < 8; nf++) {
            float p00 = __expf(Sc[nf][0] - mn0);
            float p01 = __expf(Sc[nf][1] - mn0);
            float p10 = __expf(Sc[nf][2] - mn1);
            float p11 = __expf(Sc[nf][3] - mn1);
            s0 += p00 + p01; s1 += p10 + p11;
            Pw[g * 68 + nf * 8 + 2 * tg]           = to_tf32(p00);
            Pw[g * 68 + nf * 8 + 2 * tg + 1]       = to_tf32(p01);
            Pw[(g + 8) * 68 + nf * 8 + 2 * tg]     = to_tf32(p10);
            Pw[(g + 8) * 68 + nf * 8 + 2 * tg + 1] = to_tf32(p11);
        }
        s0 += __shfl_xor_sync(0xffffffffu, s0, 1);
        s0 += __shfl_xor_sync(0xffffffffu, s0, 2);
        s1 += __shfl_xor_sync(0xffffffffu, s1, 1);
        s1 += __shfl_xor_sync(0xffffffffu, s1, 2);
        l0 = l0 * al0 + s0;
        l1 = l1 * al1 + s1;
        #pragma unroll
        for (int df = 0; df < 8; df++) {
            Ov[df][0] *= al0; Ov[df][1] *= al0;
            Ov[df][2] *= al1; Ov[df][3] *= al1;
        }
        __syncwarp();

        // O += P V
        const uint32_t* Pu = (const uint32_t*)Pw;
        #pragma unroll
        for (int ks = 0; ks < 8; ks++) {
            uint32_t a0 = Pu[g * 68 + ks * 8 + tg];
            uint32_t a1 = Pu[(g + 8) * 68 + ks * 8 + tg];
            uint32_t a2 = Pu[g * 68 + ks * 8 + tg + 4];
            uint32_t a3 = Pu[(g + 8) * 68 + ks * 8 + tg + 4];
            #pragma unroll
            for (int df = 0; df < 8; df++) {
                uint32_t b0 = Vu[(ks * 8 + tg) * 68 + df * 8 + g];
                uint32_t b1 = Vu[(ks * 8 + tg + 4) * 68 + df * 8 + g];
                mma8(Ov[df], a0, a1, a2, a3, b0, b1);
            }
        }
    }

    // epilogue
    float i0 = 1.f / l0, i1 = 1.f / l1;
    int rg0 = q0 + 16 * w + g;
    if (rg0 < L_) {
        float* o = out + ((size_t)b * L_ + rg0) * C_ + h * D_;
        #pragma unroll
        for (int df = 0; df < 8; df++)
            *(float2*)&o[df * 8 + 2 * tg] =
                make_float2(Ov[df][0] * i0, Ov[df][1] * i0);
    }
    int rg1 = rg0 + 8;
    if (rg1 < L_) {
        float* o = out + ((size_t)b * L_ + rg1) * C_ + h * D_;
        #pragma unroll
        for (int df = 0; df < 8; df++)
            *(float2*)&o[df * 8 + 2 * tg] =
                make_float2(Ov[df][2] * i1, Ov[df][3] * i1);
    }
}

// ---------------- launch ----------------
extern "C" void kernel_launch(void* const* d_in, const int* in_sizes, int n_in,
                              void* d_out, int out_size)
{
    const float* x       = (const float*)d_in[0];
    const float* q_dw    = (const float*)d_in[1];
    const float* q_scale = (const float*)d_in[2];
    const float* q_bias  = (const float*)d_in[3];
    const float* q_mean  = (const float*)d_in[4];
    const float* q_var   = (const float*)d_in[5];
    const float* q_pw    = (const float*)d_in[6];
    const float* k_dw    = (const float*)d_in[7];
    const float* k_scale = (const float*)d_in[8];
    const float* k_bias  = (const float*)d_in[9];
    const float* k_mean  = (const float*)d_in[10];
    const float* k_var   = (const float*)d_in[11];
    const float* k_pw    = (const float*)d_in[12];
    const float* v_dw    = (const float*)d_in[13];
    const float* v_scale = (const float*)d_in[14];
    const float* v_bias  = (const float*)d_in[15];
    const float* v_mean  = (const float*)d_in[16];
    const float* v_var   = (const float*)d_in[17];
    const float* v_pw    = (const float*)d_in[18];
    float* out = (float*)d_out;

    cudaFuncSetAttribute(pw_all,
                         cudaFuncAttributeMaxDynamicSharedMemorySize, PW_SMEM);
    cudaFuncSetAttribute(attn_mma,
                         cudaFuncAttributeMaxDynamicSharedMemorySize, ATTN_SMEM);

    dw_all<<<dim3(L_ + L2_, B_), C_>>>(x,
        q_dw, q_scale, q_bias, q_mean, q_var,
        k_dw, k_scale, k_bias, k_mean, k_var,
        v_dw, v_scale, v_bias, v_mean, v_var);

    pw_all<<<dim3(294, 3), 256, PW_SMEM>>>(q_pw, k_pw, v_pw);

    attn_mma<<<dim3((L_ + 127) / 128, H_, B_), 256, ATTN_SMEM>>>(out);
}

// round 6
// speedup vs baseline: 3.8040x; 1.6043x over previous
#include <cuda_runtime.h>
#include <cuda_fp16.h>
#include <math.h>
#include <stdint.h>

#define B_   8
#define S_   56
#define C_   192
#define L_   3136
#define SO_  28
#define L2_  784
#define H_   3
#define D_   64

// ---------------- scratch (no allocs allowed) ----------------
__device__ __half g_hq[B_*L_*C_];
__device__ __half g_hk[B_*L2_*C_];
__device__ __half g_hv[B_*L2_*C_];
__device__ __half g_q [B_*L_*C_];
__device__ __half g_k [B_*L2_*C_];
__device__ __half g_v [B_*L2_*C_];

// ---------------- helpers ----------------
__device__ __forceinline__ void cp16(void* dst, const void* src) {
    uint32_t d = (uint32_t)__cvta_generic_to_shared(dst);
    asm volatile("cp.async.cg.shared.global [%0], [%1], 16;" :: "r"(d), "l"(src));
}
#define CP_COMMIT()   asm volatile("cp.async.commit_group;")
#define CP_WAIT0()    asm volatile("cp.async.wait_group 0;")
#define CP_WAIT1()    asm volatile("cp.async.wait_group 1;")
#define CP_WAIT2()    asm volatile("cp.async.wait_group 2;")

// D += A(16x16) * B(16x8), fp16 inputs, fp32 accum
__device__ __forceinline__ void mma16(float* c,
                                      uint32_t a0, uint32_t a1, uint32_t a2, uint32_t a3,
                                      uint32_t b0, uint32_t b1) {
    asm volatile("mma.sync.aligned.m16n8k16.row.col.f32.f16.f16.f32 "
                 "{%0,%1,%2,%3}, {%4,%5,%6,%7}, {%8,%9}, {%0,%1,%2,%3};"
                 : "+f"(c[0]), "+f"(c[1]), "+f"(c[2]), "+f"(c[3])
                 : "r"(a0), "r"(a1), "r"(a2), "r"(a3), "r"(b0), "r"(b1));
}

// ---------------- depthwise 3x3 + BN, vectorized float4 over channels ----------------
// block (48, 4): tx = channel-quad, ty = spatial offset. grid ((L_+L2_)/4, B_)
__global__ void __launch_bounds__(192) dw_all(const float* __restrict__ x,
    const float* __restrict__ qdw, const float* __restrict__ qsc,
    const float* __restrict__ qbi, const float* __restrict__ qmu,
    const float* __restrict__ qva,
    const float* __restrict__ kdw, const float* __restrict__ ksc,
    const float* __restrict__ kbi, const float* __restrict__ kmu,
    const float* __restrict__ kva,
    const float* __restrict__ vdw, const float* __restrict__ vsc,
    const float* __restrict__ vbi, const float* __restrict__ vmu,
    const float* __restrict__ vva)
{
    const int b = blockIdx.y;
    const int sp = blockIdx.x * 4 + threadIdx.y;
    const int c = threadIdx.x * 4;
    const float* xb = x + (size_t)b * L_ * C_ + c;

    if (sp < L_) {
        // stride-1 q path: pad_lo = pad_hi = 1
        int y = sp / S_, xx = sp - y * S_;
        float4 a = make_float4(0.f, 0.f, 0.f, 0.f);
        #pragma unroll
        for (int dy = 0; dy < 3; dy++) {
            int iy = y + dy - 1;
            if ((unsigned)iy >= (unsigned)S_) continue;
            #pragma unroll
            for (int dx = 0; dx < 3; dx++) {
                int ix = xx + dx - 1;
                if ((unsigned)ix >= (unsigned)S_) continue;
                float4 xv = *(const float4*)&xb[(size_t)(iy * S_ + ix) * C_];
                float4 wv = *(const float4*)&qdw[(dy * 3 + dx) * C_ + c];
                a.x += xv.x * wv.x; a.y += xv.y * wv.y;
                a.z += xv.z * wv.z; a.w += xv.w * wv.w;
            }
        }
        float4 scv = *(const float4*)&qsc[c];
        float4 vav = *(const float4*)&qva[c];
        float4 muv = *(const float4*)&qmu[c];
        float4 biv = *(const float4*)&qbi[c];
        float r0 = (a.x - muv.x) * scv.x * rsqrtf(vav.x + 1e-5f) + biv.x;
        float r1 = (a.y - muv.y) * scv.y * rsqrtf(vav.y + 1e-5f) + biv.y;
        float r2 = (a.z - muv.z) * scv.z * rsqrtf(vav.z + 1e-5f) + biv.z;
        float r3 = (a.w - muv.w) * scv.w * rsqrtf(vav.w + 1e-5f) + biv.w;
        __half2* o = (__half2*)&g_hq[((size_t)b * L_ + sp) * C_ + c];
        o[0] = __floats2half2_rn(r0, r1);
        o[1] = __floats2half2_rn(r2, r3);
    } else {
        // stride-2 k/v path: JAX SAME 56->28: pad_lo=0, pad_hi=1
        int p2 = sp - L_;
        int y = p2 / SO_, xx = p2 - y * SO_;
        float4 ak = make_float4(0.f, 0.f, 0.f, 0.f);
        float4 av = make_float4(0.f, 0.f, 0.f, 0.f);
        #pragma unroll
        for (int dy = 0; dy < 3; dy++) {
            int iy = 2 * y + dy;
            if (iy >= S_) continue;
            #pragma unroll
            for (int dx = 0; dx < 3; dx++) {
                int ix = 2 * xx + dx;
                if (ix >= S_) continue;
                float4 xv = *(const float4*)&xb[(size_t)(iy * S_ + ix) * C_];
                float4 wk = *(const float4*)&kdw[(dy * 3 + dx) * C_ + c];
                float4 wv = *(const float4*)&vdw[(dy * 3 + dx) * C_ + c];
                ak.x += xv.x * wk.x; ak.y += xv.y * wk.y;
                ak.z += xv.z * wk.z; ak.w += xv.w * wk.w;
                av.x += xv.x * wv.x; av.y += xv.y * wv.y;
                av.z += xv.z * wv.z; av.w += xv.w * wv.w;
            }
        }
        {
            float4 scv = *(const float4*)&ksc[c];
            float4 vav = *(const float4*)&kva[c];
            float4 muv = *(const float4*)&kmu[c];
            float4 biv = *(const float4*)&kbi[c];
            float r0 = (ak.x - muv.x) * scv.x * rsqrtf(vav.x + 1e-5f) + biv.x;
            float r1 = (ak.y - muv.y) * scv.y * rsqrtf(vav.y + 1e-5f) + biv.y;
            float r2 = (ak.z - muv.z) * scv.z * rsqrtf(vav.z + 1e-5f) + biv.z;
            float r3 = (ak.w - muv.w) * scv.w * rsqrtf(vav.w + 1e-5f) + biv.w;
            __half2* o = (__half2*)&g_hk[((size_t)b * L2_ + p2) * C_ + c];
            o[0] = __floats2half2_rn(r0, r1);
            o[1] = __floats2half2_rn(r2, r3);
        }
        {
            float4 scv = *(const float4*)&vsc[c];
            float4 vav = *(const float4*)&vva[c];
            float4 muv = *(const float4*)&vmu[c];
            float4 biv = *(const float4*)&vbi[c];
            float r0 = (av.x - muv.x) * scv.x * rsqrtf(vav.x + 1e-5f) + biv.x;
            float r1 = (av.y - muv.y) * scv.y * rsqrtf(vav.y + 1e-5f) + biv.y;
            float r2 = (av.z - muv.z) * scv.z * rsqrtf(vav.z + 1e-5f) + biv.z;
            float r3 = (av.w - muv.w) * scv.w * rsqrtf(vav.w + 1e-5f) + biv.w;
            __half2* o = (__half2*)&g_hv[((size_t)b * L2_ + p2) * C_ + c];
            o[0] = __floats2half2_rn(r0, r1);
            o[1] = __floats2half2_rn(r2, r3);
        }
    }
}

// ---------------- pointwise 1x1 conv, all three projections, fp16 mma ----------------
// grid.x: [0,196) q, [196,245) k, [245,294) v; grid.y: n-block (head).
// CTA 128x64, 256 thr, warp tile 16x64, BK=16 (one k16 step), 4-deep cp.async ring.
// A smem row: 24 halfs (12 u32); B panel row: 200 halfs (100 u32).
#define PW_SMEM (4*128*24*2 + 64*200*2)
__global__ void __launch_bounds__(256) pw_all(const float* __restrict__ Wq,
                                              const float* __restrict__ Wk,
                                              const float* __restrict__ Wv)
{
    const __half* A; const float* W; __half* Cp; float oscale; int m0;
    int bx = blockIdx.x;
    if (bx < 196)      { A = g_hq; Cp = g_q; W = Wq; oscale = 0.125f; m0 = bx * 128; }
    else if (bx < 245) { A = g_hk; Cp = g_k; W = Wk; oscale = 1.0f;  m0 = (bx - 196) * 128; }
    else               { A = g_hv; Cp = g_v; W = Wv; oscale = 1.0f;  m0 = (bx - 245) * 128; }
    const int n0 = blockIdx.y * 64;

    extern __shared__ char smc[];
    __half* As = (__half*)smc;                    // 4 stages * 128*24
    __half* Bs = (__half*)(smc + 4 * 128 * 24 * 2); // 64 rows * 200

    const int tid = threadIdx.x;
    const int w = tid >> 5, lane = tid & 31;
    const int g = lane >> 2, tg = lane & 3;
    const int r0 = 16 * w + g;
    const int ar = tid >> 1, ao = (tid & 1) * 8;   // A-chunk row / half-offset

    // prefetch stages 0..2
    #pragma unroll
    for (int s = 0; s < 3; s++) {
        cp16(&As[s * 128 * 24 + ar * 24 + ao],
             A + (size_t)(m0 + ar) * C_ + s * 16 + ao);
        CP_COMMIT();
    }

    // stage full B panel transposed: Bs[n][k], fp16
    #pragma unroll 4
    for (int idx = tid; idx < 192 * 64; idx += 256) {
        int k = idx >> 6, n = idx & 63;
        Bs[n * 200 + k] = __float2half_rn(W[(size_t)k * C_ + n0 + n]);
    }

    float Cv[8][4];
    #pragma unroll
    for (int i = 0; i < 8; i++)
        #pragma unroll
        for (int j = 0; j < 4; j++) Cv[i][j] = 0.f;

    const uint32_t* Bu = (const uint32_t*)Bs;

    for (int s = 0; s < 12; s++) {
        CP_WAIT2();
        __syncthreads();
        if (s < 9) {
            cp16(&As[((s + 3) & 3) * 128 * 24 + ar * 24 + ao],
                 A + (size_t)(m0 + ar) * C_ + (s + 3) * 16 + ao);
        }
        CP_COMMIT();

        const uint32_t* Au = (const uint32_t*)(As + (s & 3) * 128 * 24);
        uint32_t a0 = Au[r0 * 12 + tg];
        uint32_t a1 = Au[(r0 + 8) * 12 + tg];
        uint32_t a2 = Au[r0 * 12 + tg + 4];
        uint32_t a3 = Au[(r0 + 8) * 12 + tg + 4];
        int kb2 = s * 8;
        #pragma unroll
        for (int nf = 0; nf < 8; nf++) {
            uint32_t b0 = Bu[(nf * 8 + g) * 100 + kb2 + tg];
            uint32_t b1 = Bu[(nf * 8 + g) * 100 + kb2 + tg + 4];
            mma16(Cv[nf], a0, a1, a2, a3, b0, b1);
        }
    }

    __half* o0 = Cp + (size_t)(m0 + r0) * C_ + n0;
    __half* o1 = o0 + (size_t)8 * C_;
    #pragma unroll
    for (int nf = 0; nf < 8; nf++) {
        *(__half2*)&o0[nf * 8 + 2 * tg] =
            __floats2half2_rn(Cv[nf][0] * oscale, Cv[nf][1] * oscale);
        *(__half2*)&o1[nf * 8 + 2 * tg] =
            __floats2half2_rn(Cv[nf][2] * oscale, Cv[nf][3] * oscale);
    }
}

// ---------------- flash attention via fp16 mma ----------------
// CTA: 128 q-rows, 8 warps x 16 rows. K-tile 64, double-buffered cp.async K,
// V via register round-trip -> transposed smem. P per-warp smem (overlays Qs).
#define NKT 13
// halfs: Qs 128*72, Ks 2*64*72, Vt 2*64*72
#define ATTN_SMEM ((128*72 + 4*64*72) * 2)
__global__ void __launch_bounds__(256) attn_mma(float* __restrict__ out)
{
    extern __shared__ char smc[];
    __half* Qs = (__half*)smc;
    __half* Ks = Qs + 128 * 72;
    __half* Vt = Ks + 2 * 64 * 72;

    const int tid = threadIdx.x;
    const int w = tid >> 5, lane = tid & 31;
    const int g = lane >> 2, tg = lane & 3;
    const int q0 = blockIdx.x * 128;
    const int h = blockIdx.y, b = blockIdx.z;

    const __half* qp = g_q + (size_t)b * L_ * C_ + h * D_;
    const __half* kp = g_k + (size_t)b * L2_ * C_ + h * D_;
    const __half* vp = g_v + (size_t)b * L2_ * C_ + h * D_;

    const int vj = tid >> 3;             // 0..31
    const int vd = (tid & 7) * 8;        // d-octet

    // prologue: Q (group 0)
    #pragma unroll
    for (int p = 0; p < 4; p++) {
        int id = tid + p * 256;
        int r = id >> 3, off = (id & 7) * 8;
        int rg = q0 + r; if (rg > L_ - 1) rg = L_ - 1;
        cp16(&Qs[r * 72 + off], qp + (size_t)rg * C_ + off);
    }
    CP_COMMIT();
    // K tile 0 (group 1)
    #pragma unroll
    for (int p = 0; p < 2; p++) {
        int id = tid + p * 256;
        int j = id >> 3, off = (id & 7) * 8;
        cp16(&Ks[j * 72 + off], kp + (size_t)j * C_ + off);
    }
    CP_COMMIT();
    // V tile 0 -> regs
    uint4 v0 = *(const uint4*)(vp + (size_t)vj * C_ + vd);
    uint4 v1 = *(const uint4*)(vp + (size_t)(vj + 32) * C_ + vd);

    CP_WAIT1();          // Q done
    __syncthreads();

    // Q fragments: 16 rows x 64 cols per warp
    uint32_t Qa[4][4];
    {
        const uint32_t* Qu = (const uint32_t*)Qs;
        #pragma unroll
        for (int ks = 0; ks < 4; ks++) {
            int r0 = 16 * w + g;
            Qa[ks][0] = Qu[r0 * 36 + ks * 8 + tg];
            Qa[ks][1] = Qu[(r0 + 8) * 36 + ks * 8 + tg];
            Qa[ks][2] = Qu[r0 * 36 + ks * 8 + tg + 4];
            Qa[ks][3] = Qu[(r0 + 8) * 36 + ks * 8 + tg + 4];
        }
    }
    // Vt tile 0 (buffer 0)
    {
        const __half* h0 = (const __half*)&v0;
        const __half* h1 = (const __half*)&v1;
        #pragma unroll
        for (int i = 0; i < 8; i++) {
            Vt[(vd + i) * 72 + vj]      = h0[i];
            Vt[(vd + i) * 72 + vj + 32] = h1[i];
        }
    }

    float Ov[8][4];
    #pragma unroll
    for (int i = 0; i < 8; i++)
        #pragma unroll
        for (int j = 0; j < 4; j++) Ov[i][j] = 0.f;
    float m0 = -1e30f, m1 = -1e30f, l0 = 0.f, l1 = 0.f;

    __half* Pw = Qs + w * 16 * 72;      // warp-private P (16 x 72 halfs)
    uint32_t* Pwu = (uint32_t*)Pw;

    for (int kt = 0; kt < NKT; kt++) {
        CP_WAIT0();                      // K tile kt arrived
        __syncthreads();                 // Vt tile kt writes + prev readers done

        if (kt + 1 < NKT) {              // prefetch K(kt+1); V(kt+1) -> regs
            int nb = (kt + 1) & 1;
            int j0n = (kt + 1) * 64;
            __half* Kb = Ks + nb * (64 * 72);
            #pragma unroll
            for (int p = 0; p < 2; p++) {
                int id = tid + p * 256;
                int j = id >> 3, off = (id & 7) * 8;
                int jg = j0n + j; if (jg > L2_ - 1) jg = L2_ - 1;
                cp16(&Kb[j * 72 + off], kp + (size_t)jg * C_ + off);
            }
            CP_COMMIT();
            int jg0 = j0n + vj;      if (jg0 > L2_ - 1) jg0 = L2_ - 1;
            int jg1 = j0n + vj + 32; if (jg1 > L2_ - 1) jg1 = L2_ - 1;
            v0 = *(const uint4*)(vp + (size_t)jg0 * C_ + vd);
            v1 = *(const uint4*)(vp + (size_t)jg1 * C_ + vd);
        }

        const uint32_t* Ku = (const uint32_t*)(Ks + (kt & 1) * (64 * 72));
        const uint32_t* Vu = (const uint32_t*)(Vt + (kt & 1) * (64 * 72));

        // S = Q K^T : warp 16 x 64
        float Sc[8][4];
        #pragma unroll
        for (int i = 0; i < 8; i++)
            #pragma unroll
            for (int j = 0; j < 4; j++) Sc[i][j] = 0.f;
        #pragma unroll
        for (int ks = 0; ks < 4; ks++) {
            #pragma unroll
            for (int nf = 0; nf < 8; nf++) {
                uint32_t b0 = Ku[(nf * 8 + g) * 36 + ks * 8 + tg];
                uint32_t b1 = Ku[(nf * 8 + g) * 36 + ks * 8 + tg + 4];
                mma16(Sc[nf], Qa[ks][0], Qa[ks][1], Qa[ks][2], Qa[ks][3], b0, b1);
            }
        }

        int j0 = kt * 64;
        if (j0 + 64 > L2_) {             // mask invalid keys (last tile)
            #pragma unroll
            for (int nf = 0; nf < 8; nf++) {
                int c0 = j0 + nf * 8 + 2 * tg;
                if (c0 >= L2_)     { Sc[nf][0] = -1e30f; Sc[nf][2] = -1e30f; }
                if (c0 + 1 >= L2_) { Sc[nf][1] = -1e30f; Sc[nf][3] = -1e30f; }
            }
        }

        // online softmax (rows g / g+8; col reduce over quad lanes xor 1,2)
        float mx0 = -1e30f, mx1 = -1e30f;
        #pragma unroll
        for (int nf = 0; nf < 8; nf++) {
            mx0 = fmaxf(mx0, fmaxf(Sc[nf][0], Sc[nf][1]));
            mx1 = fmaxf(mx1, fmaxf(Sc[nf][2], Sc[nf][3]));
        }
        mx0 = fmaxf(mx0, __shfl_xor_sync(0xffffffffu, mx0, 1));
        mx0 = fmaxf(mx0, __shfl_xor_sync(0xffffffffu, mx0, 2));
        mx1 = fmaxf(mx1, __shfl_xor_sync(0xffffffffu, mx1, 1));
        mx1 = fmaxf(mx1, __shfl_xor_sync(0xffffffffu, mx1, 2));
        float mn0 = fmaxf(m0, mx0), mn1 = fmaxf(m1, mx1);
        float al0 = __expf(m0 - mn0), al1 = __expf(m1 - mn1);
        m0 = mn0; m1 = mn1;
        float s0 = 0.f, s1 = 0.f;
        #pragma unroll
        for (int nf = 0; nf < 8; nf++) {
            float p00 = __expf(Sc[nf][0] - mn0);
            float p01 = __expf(Sc[nf][1] - mn0);
            float p10 = __expf(Sc[nf][2] - mn1);
            float p11 = __expf(Sc[nf][3] - mn1);
            s0 += p00 + p01; s1 += p10 + p11;
            __half2 hp0 = __floats2half2_rn(p00, p01);
            __half2 hp1 = __floats2half2_rn(p10, p11);
            Pwu[g * 36 + nf * 4 + tg]       = *(uint32_t*)&hp0;
            Pwu[(g + 8) * 36 + nf * 4 + tg] = *(uint32_t*)&hp1;
        }
        s0 += __shfl_xor_sync(0xffffffffu, s0, 1);
        s0 += __shfl_xor_sync(0xffffffffu, s0, 2);
        s1 += __shfl_xor_sync(0xffffffffu, s1, 1);
        s1 += __shfl_xor_sync(0xffffffffu, s1, 2);
        l0 = l0 * al0 + s0;
        l1 = l1 * al1 + s1;
        #pragma unroll
        for (int df = 0; df < 8; df++) {
            Ov[df][0] *= al0; Ov[df][1] *= al0;
            Ov[df][2] *= al1; Ov[df][3] *= al1;
        }
        __syncwarp();

        // O += P V   (A = P from warp smem, B = Vt)
        #pragma unroll
        for (int ks = 0; ks < 4; ks++) {
            uint32_t a0 = Pwu[g * 36 + ks * 8 + tg];
            uint32_t a1 = Pwu[(g + 8) * 36 + ks * 8 + tg];
            uint32_t a2 = Pwu[g * 36 + ks * 8 + tg + 4];
            uint32_t a3 = Pwu[(g + 8) * 36 + ks * 8 + tg + 4];
            #pragma unroll
            for (int df = 0; df < 8; df++) {
                uint32_t b0 = Vu[(df * 8 + g) * 36 + ks * 8 + tg];
                uint32_t b1 = Vu[(df * 8 + g) * 36 + ks * 8 + tg + 4];
                mma16(Ov[df], a0, a1, a2, a3, b0, b1);
            }
        }

        // write Vt tile kt+1 into the other buffer
        if (kt + 1 < NKT) {
            __half* Vb = Vt + ((kt + 1) & 1) * (64 * 72);
            const __half* h0 = (const __half*)&v0;
            const __half* h1 = (const __half*)&v1;
            #pragma unroll
            for (int i = 0; i < 8; i++) {
                Vb[(vd + i) * 72 + vj]      = h0[i];
                Vb[(vd + i) * 72 + vj + 32] = h1[i];
            }
        }
    }

    // epilogue (fp32 output)
    float i0 = 1.f / l0, i1 = 1.f / l1;
    int rg0 = q0 + 16 * w + g;
    if (rg0 < L_) {
        float* o = out + ((size_t)b * L_ + rg0) * C_ + h * D_;
        #pragma unroll
        for (int df = 0; df < 8; df++)
            *(float2*)&o[df * 8 + 2 * tg] =
                make_float2(Ov[df][0] * i0, Ov[df][1] * i0);
    }
    int rg1 = rg0 + 8;
    if (rg1 < L_) {
        float* o = out + ((size_t)b * L_ + rg1) * C_ + h * D_;
        #pragma unroll
        for (int df = 0; df < 8; df++)
            *(float2*)&o[df * 8 + 2 * tg] =
                make_float2(Ov[df][2] * i1, Ov[df][3] * i1);
    }
}

// ---------------- launch ----------------
extern "C" void kernel_launch(void* const* d_in, const int* in_sizes, int n_in,
                              void* d_out, int out_size)
{
    const float* x       = (const float*)d_in[0];
    const float* q_dw    = (const float*)d_in[1];
    const float* q_scale = (const float*)d_in[2];
    const float* q_bias  = (const float*)d_in[3];
    const float* q_mean  = (const float*)d_in[4];
    const float* q_var   = (const float*)d_in[5];
    const float* q_pw    = (const float*)d_in[6];
    const float* k_dw    = (const float*)d_in[7];
    const float* k_scale = (const float*)d_in[8];
    const float* k_bias  = (const float*)d_in[9];
    const float* k_mean  = (const float*)d_in[10];
    const float* k_var   = (const float*)d_in[11];
    const float* k_pw    = (const float*)d_in[12];
    const float* v_dw    = (const float*)d_in[13];
    const float* v_scale = (const float*)d_in[14];
    const float* v_bias  = (const float*)d_in[15];
    const float* v_mean  = (const float*)d_in[16];
    const float* v_var   = (const float*)d_in[17];
    const float* v_pw    = (const float*)d_in[18];
    float* out = (float*)d_out;

    cudaFuncSetAttribute(pw_all,
                         cudaFuncAttributeMaxDynamicSharedMemorySize, PW_SMEM);
    cudaFuncSetAttribute(attn_mma,
                         cudaFuncAttributeMaxDynamicSharedMemorySize, ATTN_SMEM);

    dw_all<<<dim3((L_ + L2_) / 4, B_), dim3(48, 4)>>>(x,
        q_dw, q_scale, q_bias, q_mean, q_var,
        k_dw, k_scale, k_bias, k_mean, k_var,
        v_dw, v_scale, v_bias, v_mean, v_var);

    pw_all<<<dim3(294, 3), 256, PW_SMEM>>>(q_pw, k_pw, v_pw);

    attn_mma<<<dim3((L_ + 127) / 128, H_, B_), 256, ATTN_SMEM>>>(out);
}

// round 7
// speedup vs baseline: 3.9689x; 1.0433x over previous
#include <cuda_runtime.h>
#include <cuda_fp16.h>
#include <math.h>
#include <stdint.h>

#define B_   8
#define S_   56
#define C_   192
#define L_   3136
#define SO_  28
#define L2_  784
#define H_   3
#define D_   64

// ---------------- scratch (no allocs allowed) ----------------
__device__ __half g_hq[B_*L_*C_];
__device__ __half g_hk[B_*L2_*C_];
__device__ __half g_hv[B_*L2_*C_];
__device__ __half g_q [B_*L_*C_];
__device__ __half g_k [B_*L2_*C_];
__device__ __half g_v [B_*L2_*C_];

// ---------------- helpers ----------------
__device__ __forceinline__ void cp16(void* dst, const void* src) {
    uint32_t d = (uint32_t)__cvta_generic_to_shared(dst);
    asm volatile("cp.async.cg.shared.global [%0], [%1], 16;" :: "r"(d), "l"(src));
}
#define CP_COMMIT()   asm volatile("cp.async.commit_group;")
#define CP_WAIT0()    asm volatile("cp.async.wait_group 0;")
#define CP_WAIT1()    asm volatile("cp.async.wait_group 1;")

__device__ __forceinline__ uint32_t smem_u32(const void* p) {
    return (uint32_t)__cvta_generic_to_shared(p);
}
__device__ __forceinline__ float ex2(float x) {
    float r;
    asm("ex2.approx.f32 %0, %1;" : "=f"(r) : "f"(x));
    return r;
}

// D += A(16x16) * B(16x8), fp16 inputs, fp32 accum
__device__ __forceinline__ void mma16(float* c,
                                      uint32_t a0, uint32_t a1, uint32_t a2, uint32_t a3,
                                      uint32_t b0, uint32_t b1) {
    asm volatile("mma.sync.aligned.m16n8k16.row.col.f32.f16.f16.f32 "
                 "{%0,%1,%2,%3}, {%4,%5,%6,%7}, {%8,%9}, {%0,%1,%2,%3};"
                 : "+f"(c[0]), "+f"(c[1]), "+f"(c[2]), "+f"(c[3])
                 : "r"(a0), "r"(a1), "r"(a2), "r"(a3), "r"(b0), "r"(b1));
}
#define LDM_X4(d0,d1,d2,d3,a) \
    asm volatile("ldmatrix.sync.aligned.m8n8.x4.shared.b16 {%0,%1,%2,%3}, [%4];" \
                 : "=r"(d0), "=r"(d1), "=r"(d2), "=r"(d3) : "r"(a))
#define LDM_X4T(d0,d1,d2,d3,a) \
    asm volatile("ldmatrix.sync.aligned.m8n8.x4.trans.shared.b16 {%0,%1,%2,%3}, [%4];" \
                 : "=r"(d0), "=r"(d1), "=r"(d2), "=r"(d3) : "r"(a))

// log2(e) folded into q projection scale: scores land in exp2 domain.
#define QSCALE (0.125f * 1.44269504088896f)

// ---------------- depthwise 3x3 + BN, vertical multi-output columns ----------------
// block (48,4): tx = channel quad, ty = strip select. grid (294, B_).
// strips 0..783: q path, 4-tall column; 784..1175: k/v path, 2-tall column.
__global__ void __launch_bounds__(192) dw_all(const float* __restrict__ x,
    const float* __restrict__ qdw, const float* __restrict__ qsc,
    const float* __restrict__ qbi, const float* __restrict__ qmu,
    const float* __restrict__ qva,
    const float* __restrict__ kdw, const float* __restrict__ ksc,
    const float* __restrict__ kbi, const float* __restrict__ kmu,
    const float* __restrict__ kva,
    const float* __restrict__ vdw, const float* __restrict__ vsc,
    const float* __restrict__ vbi, const float* __restrict__ vmu,
    const float* __restrict__ vva)
{
    const int b = blockIdx.y;
    const int p = blockIdx.x * 4 + threadIdx.y;
    const int c = threadIdx.x * 4;
    const float* xb = x + (size_t)b * L_ * C_ + c;

    if (p < 784) {
        // q path: outputs (y0..y0+3, xx); input rows y0-1 .. y0+4, pad 1 both sides
        int y0 = (p / 56) * 4, xx = p % 56;
        float4 acc[4];
        #pragma unroll
        for (int i = 0; i < 4; i++) acc[i] = make_float4(0.f, 0.f, 0.f, 0.f);
        #pragma unroll
        for (int r = 0; r < 6; r++) {
            int iy = y0 - 1 + r;
            if ((unsigned)iy >= (unsigned)S_) continue;
            #pragma unroll
            for (int dx = 0; dx < 3; dx++) {
                int ix = xx + dx - 1;
                if ((unsigned)ix >= (unsigned)S_) continue;
                float4 xv = *(const float4*)&xb[(size_t)(iy * S_ + ix) * C_];
                #pragma unroll
                for (int i = 0; i < 4; i++) {
                    int dy = r - i;
                    if (dy < 0 || dy > 2) continue;
                    float4 wv = *(const float4*)&qdw[(dy * 3 + dx) * C_ + c];
                    acc[i].x += xv.x * wv.x; acc[i].y += xv.y * wv.y;
                    acc[i].z += xv.z * wv.z; acc[i].w += xv.w * wv.w;
                }
            }
        }
        float4 scv = *(const float4*)&qsc[c];
        float4 vav = *(const float4*)&qva[c];
        float4 muv = *(const float4*)&qmu[c];
        float4 biv = *(const float4*)&qbi[c];
        float a0 = scv.x * rsqrtf(vav.x + 1e-5f);
        float a1 = scv.y * rsqrtf(vav.y + 1e-5f);
        float a2 = scv.z * rsqrtf(vav.z + 1e-5f);
        float a3 = scv.w * rsqrtf(vav.w + 1e-5f);
        #pragma unroll
        for (int i = 0; i < 4; i++) {
            __half2* o = (__half2*)&g_hq[((size_t)b * L_ + (y0 + i) * S_ + xx) * C_ + c];
            o[0] = __floats2half2_rn((acc[i].x - muv.x) * a0 + biv.x,
                                     (acc[i].y - muv.y) * a1 + biv.y);
            o[1] = __floats2half2_rn((acc[i].z - muv.z) * a2 + biv.z,
                                     (acc[i].w - muv.w) * a3 + biv.w);
        }
    } else {
        // k/v path: outputs (y0, y0+1) at xx; iy = 2*yo + dy (pad_lo=0, pad_hi=1)
        int p2 = p - 784;
        int y0 = (p2 / SO_) * 2, xx = p2 % SO_;
        float4 ka[2], va[2];
        #pragma unroll
        for (int i = 0; i < 2; i++) {
            ka[i] = make_float4(0.f, 0.f, 0.f, 0.f);
            va[i] = make_float4(0.f, 0.f, 0.f, 0.f);
        }
        #pragma unroll
        for (int r = 0; r < 5; r++) {
            int iy = 2 * y0 + r;
            if (iy >= S_) continue;
            #pragma unroll
            for (int dx = 0; dx < 3; dx++) {
                int ix = 2 * xx + dx;
                if (ix >= S_) continue;
                float4 xv = *(const float4*)&xb[(size_t)(iy * S_ + ix) * C_];
                #pragma unroll
                for (int i = 0; i < 2; i++) {
                    int dy = r - 2 * i;
                    if (dy < 0 || dy > 2) continue;
                    float4 wk = *(const float4*)&kdw[(dy * 3 + dx) * C_ + c];
                    float4 wv = *(const float4*)&vdw[(dy * 3 + dx) * C_ + c];
                    ka[i].x += xv.x * wk.x; ka[i].y += xv.y * wk.y;
                    ka[i].z += xv.z * wk.z; ka[i].w += xv.w * wk.w;
                    va[i].x += xv.x * wv.x; va[i].y += xv.y * wv.y;
                    va[i].z += xv.z * wv.z; va[i].w += xv.w * wv.w;
                }
            }
        }
        {
            float4 scv = *(const float4*)&ksc[c];
            float4 vav = *(const float4*)&kva[c];
            float4 muv = *(const float4*)&kmu[c];
            float4 biv = *(const float4*)&kbi[c];
            float a0 = scv.x * rsqrtf(vav.x + 1e-5f);
            float a1 = scv.y * rsqrtf(vav.y + 1e-5f);
            float a2 = scv.z * rsqrtf(vav.z + 1e-5f);
            float a3 = scv.w * rsqrtf(vav.w + 1e-5f);
            #pragma unroll
            for (int i = 0; i < 2; i++) {
                __half2* o = (__half2*)&g_hk[((size_t)b * L2_ + (y0 + i) * SO_ + xx) * C_ + c];
                o[0] = __floats2half2_rn((ka[i].x - muv.x) * a0 + biv.x,
                                         (ka[i].y - muv.y) * a1 + biv.y);
                o[1] = __floats2half2_rn((ka[i].z - muv.z) * a2 + biv.z,
                                         (ka[i].w - muv.w) * a3 + biv.w);
            }
        }
        {
            float4 scv = *(const float4*)&vsc[c];
            float4 vav = *(const float4*)&vva[c];
            float4 muv = *(const float4*)&vmu[c];
            float4 biv = *(const float4*)&vbi[c];
            float a0 = scv.x * rsqrtf(vav.x + 1e-5f);
            float a1 = scv.y * rsqrtf(vav.y + 1e-5f);
            float a2 = scv.z * rsqrtf(vav.z + 1e-5f);
            float a3 = scv.w * rsqrtf(vav.w + 1e-5f);
            #pragma unroll
            for (int i = 0; i < 2; i++) {
                __half2* o = (__half2*)&g_hv[((size_t)b * L2_ + (y0 + i) * SO_ + xx) * C_ + c];
                o[0] = __floats2half2_rn((va[i].x - muv.x) * a0 + biv.x,
                                         (va[i].y - muv.y) * a1 + biv.y);
                o[1] = __floats2half2_rn((va[i].z - muv.z) * a2 + biv.z,
                                         (va[i].w - muv.w) * a3 + biv.w);
            }
        }
    }
}

// ---------------- pointwise 1x1 conv: whole-tile staging, single barrier ----------------
// grid.x: [0,196) q, [196,245) k, [245,294) v; grid.y: n-block (head) of 64.
// As[128][200] halfs (cp.async), Bs[192][72] halfs k-major (ldmatrix.trans fragments).
#define PW_SMEM (128*200*2 + 192*72*2)
__global__ void __launch_bounds__(256) pw_all(const float* __restrict__ Wq,
                                              const float* __restrict__ Wk,
                                              const float* __restrict__ Wv)
{
    const __half* A; const float* W; __half* Cp; float oscale; int m0;
    int bx = blockIdx.x;
    if (bx < 196)      { A = g_hq; Cp = g_q; W = Wq; oscale = QSCALE; m0 = bx * 128; }
    else if (bx < 245) { A = g_hk; Cp = g_k; W = Wk; oscale = 1.0f;  m0 = (bx - 196) * 128; }
    else               { A = g_hv; Cp = g_v; W = Wv; oscale = 1.0f;  m0 = (bx - 245) * 128; }
    const int n0 = blockIdx.y * 64;

    extern __shared__ char smc[];
    __half* As = (__half*)smc;                    // 128 x 200
    __half* Bs = (__half*)(smc + 128 * 200 * 2);  // 192 x 72 (k-major)

    const int tid = threadIdx.x;
    const int w = tid >> 5, lane = tid & 31;
    const int g = lane >> 2, tg = lane & 3;
    const int lm = lane >> 3, lr = lane & 7;
    const uint32_t sAs = smem_u32(As), sBs = smem_u32(Bs);

    // A tile via cp.async: 128 rows x 24 16B-chunks
    #pragma unroll
    for (int i = 0; i < 12; i++) {
        int idx = tid + i * 256;
        int r = idx / 24, ch = idx % 24;
        cp16(&As[r * 200 + ch * 8], A + (size_t)(m0 + r) * C_ + ch * 8);
    }
    CP_COMMIT();

    // B panel, coalesced: W row k, 16 float4 of n
    #pragma unroll
    for (int i = 0; i < 12; i++) {
        int idx = tid + i * 256;
        int k = idx >> 4, nq = idx & 15;
        float4 wv = *(const float4*)&W[(size_t)k * C_ + n0 + nq * 4];
        __half2 h01 = __floats2half2_rn(wv.x, wv.y);
        __half2 h23 = __floats2half2_rn(wv.z, wv.w);
        uint2 u; u.x = *(uint32_t*)&h01; u.y = *(uint32_t*)&h23;
        *(uint2*)&Bs[k * 72 + nq * 4] = u;
    }
    CP_WAIT0();
    __syncthreads();

    float Cv[8][4];
    #pragma unroll
    for (int i = 0; i < 8; i++)
        #pragma unroll
        for (int j = 0; j < 4; j++) Cv[i][j] = 0.f;

    // lane-invariant parts of ldmatrix addresses
    const uint32_t aBase = sAs + (uint32_t)(((w * 16 + (lm & 1) * 8 + lr) * 200
                                             + (lm >> 1) * 8) * 2);
    const uint32_t bRow  = (uint32_t)(((lm & 1) * 8 + lr) * 72) * 2;  // k-row part
    #pragma unroll
    for (int ks = 0; ks < 12; ks++) {
        uint32_t a0, a1, a2, a3;
        LDM_X4(a0, a1, a2, a3, aBase + ks * 32);
        #pragma unroll
        for (int nfp = 0; nfp < 4; nfp++) {
            uint32_t b00, b01, b10, b11;
            uint32_t ba = sBs + (uint32_t)(ks * 16 * 72 * 2) + bRow
                        + (uint32_t)(((nfp * 2 + (lm >> 1)) * 8) * 2);
            LDM_X4T(b00, b01, b10, b11, ba);
            mma16(Cv[nfp * 2],     a0, a1, a2, a3, b00, b01);
            mma16(Cv[nfp * 2 + 1], a0, a1, a2, a3, b10, b11);
        }
    }

    const int r0 = 16 * w + g;
    __half* o0 = Cp + (size_t)(m0 + r0) * C_ + n0;
    __half* o1 = o0 + (size_t)8 * C_;
    #pragma unroll
    for (int nf = 0; nf < 8; nf++) {
        *(__half2*)&o0[nf * 8 + 2 * tg] =
            __floats2half2_rn(Cv[nf][0] * oscale, Cv[nf][1] * oscale);
        *(__half2*)&o1[nf * 8 + 2 * tg] =
            __floats2half2_rn(Cv[nf][2] * oscale, Cv[nf][3] * oscale);
    }
}

// ---------------- flash attention, fp16 mma + ldmatrix, exp2 domain ----------------
#define NKT 13
#define ATTN_SMEM ((128*72 + 4*64*72) * 2)
__global__ void __launch_bounds__(256) attn_mma(float* __restrict__ out)
{
    extern __shared__ char smc[];
    __half* Qs = (__half*)smc;
    __half* Ks = Qs + 128 * 72;
    __half* Vt = Ks + 2 * 64 * 72;

    const int tid = threadIdx.x;
    const int w = tid >> 5, lane = tid & 31;
    const int g = lane >> 2, tg = lane & 3;
    const int lm = lane >> 3, lr = lane & 7;
    const int q0 = blockIdx.x * 128;
    const int h = blockIdx.y, b = blockIdx.z;

    const __half* qp = g_q + (size_t)b * L_ * C_ + h * D_;
    const __half* kp = g_k + (size_t)b * L2_ * C_ + h * D_;
    const __half* vp = g_v + (size_t)b * L2_ * C_ + h * D_;

    const int vj = tid >> 3;             // 0..31
    const int vd = (tid & 7) * 8;        // d-octet

    // prologue: Q (group 0)
    #pragma unroll
    for (int p = 0; p < 4; p++) {
        int id = tid + p * 256;
        int r = id >> 3, off = (id & 7) * 8;
        int rg = q0 + r; if (rg > L_ - 1) rg = L_ - 1;
        cp16(&Qs[r * 72 + off], qp + (size_t)rg * C_ + off);
    }
    CP_COMMIT();
    // K tile 0 (group 1)
    #pragma unroll
    for (int p = 0; p < 2; p++) {
        int id = tid + p * 256;
        int j = id >> 3, off = (id & 7) * 8;
        cp16(&Ks[j * 72 + off], kp + (size_t)j * C_ + off);
    }
    CP_COMMIT();
    // V tile 0 -> regs
    uint4 v0 = *(const uint4*)(vp + (size_t)vj * C_ + vd);
    uint4 v1 = *(const uint4*)(vp + (size_t)(vj + 32) * C_ + vd);

    CP_WAIT1();          // Q done
    __syncthreads();

    // Q fragments via ldmatrix (16 rows x 64 cols per warp)
    const uint32_t sQ = smem_u32(Qs);
    uint32_t Qa[4][4];
    {
        uint32_t base = sQ + (uint32_t)(((w * 16 + (lm & 1) * 8 + lr) * 72
                                         + (lm >> 1) * 8) * 2);
        #pragma unroll
        for (int ks = 0; ks < 4; ks++)
            LDM_X4(Qa[ks][0], Qa[ks][1], Qa[ks][2], Qa[ks][3], base + ks * 32);
    }
    // Vt tile 0 (buffer 0)
    {
        const __half* h0 = (const __half*)&v0;
        const __half* h1 = (const __half*)&v1;
        #pragma unroll
        for (int i = 0; i < 8; i++) {
            Vt[(vd + i) * 72 + vj]      = h0[i];
            Vt[(vd + i) * 72 + vj + 32] = h1[i];
        }
    }

    float Ov[8][4];
    #pragma unroll
    for (int i = 0; i < 8; i++)
        #pragma unroll
        for (int j = 0; j < 4; j++) Ov[i][j] = 0.f;
    float m0 = -1e30f, m1 = -1e30f, l0 = 0.f, l1 = 0.f;

    __half* Pw = Qs + w * 16 * 72;      // warp-private P (16 x 72 halfs)
    uint32_t* Pwu = (uint32_t*)Pw;
    const uint32_t sP = smem_u32(Pw);
    // lane-dependent ldmatrix row offsets
    const uint32_t bRow = (uint32_t)((((lm >> 1)) * 8 + lr) * 72 * 2); // n-block row part (B ops)
    const uint32_t pBase = sP + (uint32_t)((((lm & 1) * 8 + lr) * 72 + (lm >> 1) * 8) * 2);

    for (int kt = 0; kt < NKT; kt++) {
        CP_WAIT0();                      // K tile kt arrived
        __syncthreads();                 // Vt tile kt writes + prev readers done

        if (kt + 1 < NKT) {              // prefetch K(kt+1); V(kt+1) -> regs
            int nb = (kt + 1) & 1;
            int j0n = (kt + 1) * 64;
            __half* Kb = Ks + nb * (64 * 72);
            #pragma unroll
            for (int p = 0; p < 2; p++) {
                int id = tid + p * 256;
                int j = id >> 3, off = (id & 7) * 8;
                int jg = j0n + j; if (jg > L2_ - 1) jg = L2_ - 1;
                cp16(&Kb[j * 72 + off], kp + (size_t)jg * C_ + off);
            }
            CP_COMMIT();
            int jg0 = j0n + vj;      if (jg0 > L2_ - 1) jg0 = L2_ - 1;
            int jg1 = j0n + vj + 32; if (jg1 > L2_ - 1) jg1 = L2_ - 1;
            v0 = *(const uint4*)(vp + (size_t)jg0 * C_ + vd);
            v1 = *(const uint4*)(vp + (size_t)jg1 * C_ + vd);
        }

        const uint32_t sK = smem_u32(Ks + (kt & 1) * (64 * 72));
        const uint32_t sV = smem_u32(Vt + (kt & 1) * (64 * 72));

        // S = Q K^T : warp 16 x 64
        float Sc[8][4];
        #pragma unroll
        for (int i = 0; i < 8; i++)
            #pragma unroll
            for (int j = 0; j < 4; j++) Sc[i][j] = 0.f;
        #pragma unroll
        for (int ks = 0; ks < 4; ks++) {
            #pragma unroll
            for (int nfp = 0; nfp < 4; nfp++) {
                uint32_t b00, b01, b10, b11;
                uint32_t ba = sK + (uint32_t)(nfp * 16 * 72 * 2) + bRow
                            + (uint32_t)((ks * 16 + (lm & 1) * 8) * 2);
                LDM_X4(b00, b01, b10, b11, ba);
                mma16(Sc[nfp * 2],     Qa[ks][0], Qa[ks][1], Qa[ks][2], Qa[ks][3], b00, b01);
                mma16(Sc[nfp * 2 + 1], Qa[ks][0], Qa[ks][1], Qa[ks][2], Qa[ks][3], b10, b11);
            }
        }

        int j0 = kt * 64;
        if (j0 + 64 > L2_) {             // mask invalid keys (last tile)
            #pragma unroll
            for (int nf = 0; nf < 8; nf++) {
                int c0 = j0 + nf * 8 + 2 * tg;
                if (c0 >= L2_)     { Sc[nf][0] = -1e30f; Sc[nf][2] = -1e30f; }
                if (c0 + 1 >= L2_) { Sc[nf][1] = -1e30f; Sc[nf][3] = -1e30f; }
            }
        }

        // online softmax in exp2 domain (rows g / g+8; quad reduce xor 1,2)
        float mx0 = -1e30f, mx1 = -1e30f;
        #pragma unroll
        for (int nf = 0; nf < 8; nf++) {
            mx0 = fmaxf(mx0, fmaxf(Sc[nf][0], Sc[nf][1]));
            mx1 = fmaxf(mx1, fmaxf(Sc[nf][2], Sc[nf][3]));
        }
        mx0 = fmaxf(mx0, __shfl_xor_sync(0xffffffffu, mx0, 1));
        mx0 = fmaxf(mx0, __shfl_xor_sync(0xffffffffu, mx0, 2));
        mx1 = fmaxf(mx1, __shfl_xor_sync(0xffffffffu, mx1, 1));
        mx1 = fmaxf(mx1, __shfl_xor_sync(0xffffffffu, mx1, 2));
        float mn0 = fmaxf(m0, mx0), mn1 = fmaxf(m1, mx1);
        float al0 = ex2(m0 - mn0), al1 = ex2(m1 - mn1);
        m0 = mn0; m1 = mn1;
        float s0 = 0.f, s1 = 0.f;
        #pragma unroll
        for (int nf = 0; nf < 8; nf++) {
            float p00 = ex2(Sc[nf][0] - mn0);
            float p01 = ex2(Sc[nf][1] - mn0);
            float p10 = ex2(Sc[nf][2] - mn1);
            float p11 = ex2(Sc[nf][3] - mn1);
            s0 += p00 + p01; s1 += p10 + p11;
            __half2 hp0 = __floats2half2_rn(p00, p01);
            __half2 hp1 = __floats2half2_rn(p10, p11);
            Pwu[g * 36 + nf * 4 + tg]       = *(uint32_t*)&hp0;
            Pwu[(g + 8) * 36 + nf * 4 + tg] = *(uint32_t*)&hp1;
        }
        s0 += __shfl_xor_sync(0xffffffffu, s0, 1);
        s0 += __shfl_xor_sync(0xffffffffu, s0, 2);
        s1 += __shfl_xor_sync(0xffffffffu, s1, 1);
        s1 += __shfl_xor_sync(0xffffffffu, s1, 2);
        l0 = l0 * al0 + s0;
        l1 = l1 * al1 + s1;
        #pragma unroll
        for (int df = 0; df < 8; df++) {
            Ov[df][0] *= al0; Ov[df][1] *= al0;
            Ov[df][2] *= al1; Ov[df][3] *= al1;
        }
        __syncwarp();

        // O += P V  (A = P via ldmatrix, B = Vt via ldmatrix)
        #pragma unroll
        for (int ks = 0; ks < 4; ks++) {
            uint32_t a0, a1, a2, a3;
            LDM_X4(a0, a1, a2, a3, pBase + ks * 32);
            #pragma unroll
            for (int dfp = 0; dfp < 4; dfp++) {
                uint32_t b00, b01, b10, b11;
                uint32_t ba = sV + (uint32_t)(dfp * 16 * 72 * 2) + bRow
                            + (uint32_t)((ks * 16 + (lm & 1) * 8) * 2);
                LDM_X4(b00, b01, b10, b11, ba);
                mma16(Ov[dfp * 2],     a0, a1, a2, a3, b00, b01);
                mma16(Ov[dfp * 2 + 1], a0, a1, a2, a3, b10, b11);
            }
        }

        // write Vt tile kt+1 into the other buffer
        if (kt + 1 < NKT) {
            __half* Vb = Vt + ((kt + 1) & 1) * (64 * 72);
            const __half* h0 = (const __half*)&v0;
            const __half* h1 = (const __half*)&v1;
            #pragma unroll
            for (int i = 0; i < 8; i++) {
                Vb[(vd + i) * 72 + vj]      = h0[i];
                Vb[(vd + i) * 72 + vj + 32] = h1[i];
            }
        }
    }

    // epilogue (fp32 output)
    float i0 = 1.f / l0, i1 = 1.f / l1;
    int rg0 = q0 + 16 * w + g;
    if (rg0 < L_) {
        float* o = out + ((size_t)b * L_ + rg0) * C_ + h * D_;
        #pragma unroll
        for (int df = 0; df < 8; df++)
            *(float2*)&o[df * 8 + 2 * tg] =
                make_float2(Ov[df][0] * i0, Ov[df][1] * i0);
    }
    int rg1 = rg0 + 8;
    if (rg1 < L_) {
        float* o = out + ((size_t)b * L_ + rg1) * C_ + h * D_;
        #pragma unroll
        for (int df = 0; df < 8; df++)
            *(float2*)&o[df * 8 + 2 * tg] =
                make_float2(Ov[df][2] * i1, Ov[df][3] * i1);
    }
}

// ---------------- launch ----------------
extern "C" void kernel_launch(void* const* d_in, const int* in_sizes, int n_in,
                              void* d_out, int out_size)
{
    const float* x       = (const float*)d_in[0];
    const float* q_dw    = (const float*)d_in[1];
    const float* q_scale = (const float*)d_in[2];
    const float* q_bias  = (const float*)d_in[3];
    const float* q_mean  = (const float*)d_in[4];
    const float* q_var   = (const float*)d_in[5];
    const float* q_pw    = (const float*)d_in[6];
    const float* k_dw    = (const float*)d_in[7];
    const float* k_scale = (const float*)d_in[8];
    const float* k_bias  = (const float*)d_in[9];
    const float* k_mean  = (const float*)d_in[10];
    const float* k_var   = (const float*)d_in[11];
    const float* k_pw    = (const float*)d_in[12];
    const float* v_dw    = (const float*)d_in[13];
    const float* v_scale = (const float*)d_in[14];
    const float* v_bias  = (const float*)d_in[15];
    const float* v_mean  = (const float*)d_in[16];
    const float* v_var   = (const float*)d_in[17];
    const float* v_pw    = (const float*)d_in[18];
    float* out = (float*)d_out;

    cudaFuncSetAttribute(pw_all,
                         cudaFuncAttributeMaxDynamicSharedMemorySize, PW_SMEM);
    cudaFuncSetAttribute(attn_mma,
                         cudaFuncAttributeMaxDynamicSharedMemorySize, ATTN_SMEM);

    dw_all<<<dim3(294, B_), dim3(48, 4)>>>(x,
        q_dw, q_scale, q_bias, q_mean, q_var,
        k_dw, k_scale, k_bias, k_mean, k_var,
        v_dw, v_scale, v_bias, v_mean, v_var);

    pw_all<<<dim3(294, 3), 256, PW_SMEM>>>(q_pw, k_pw, v_pw);

    attn_mma<<<dim3((L_ + 127) / 128, H_, B_), 256, ATTN_SMEM>>>(out);
}

// round 8
// speedup vs baseline: 5.8545x; 1.4751x over previous
#include <cuda_runtime.h>
#include <cuda_fp16.h>
#include <math.h>
#include <stdint.h>

#define B_   8
#define S_   56
#define C_   192
#define L_   3136
#define SO_  28
#define L2_  784
#define H_   3
#define D_   64

// ---------------- scratch (no allocs allowed) ----------------
__device__ __half g_hq[B_*L_*C_];
__device__ __half g_hk[B_*L2_*C_];
__device__ __half g_hv[B_*L2_*C_];
__device__ __half g_q [B_*L_*C_];
__device__ __half g_k [B_*L2_*C_];
__device__ __half g_v [B_*L2_*C_];

// ---------------- helpers ----------------
__device__ __forceinline__ void cp16(void* dst, const void* src) {
    uint32_t d = (uint32_t)__cvta_generic_to_shared(dst);
    asm volatile("cp.async.cg.shared.global [%0], [%1], 16;" :: "r"(d), "l"(src));
}
#define CP_COMMIT()   asm volatile("cp.async.commit_group;")
#define CP_WAIT0()    asm volatile("cp.async.wait_group 0;")
#define CP_WAIT1()    asm volatile("cp.async.wait_group 1;")

__device__ __forceinline__ uint32_t smem_u32(const void* p) {
    return (uint32_t)__cvta_generic_to_shared(p);
}
__device__ __forceinline__ float ex2(float x) {
    float r;
    asm("ex2.approx.f32 %0, %1;" : "=f"(r) : "f"(x));
    return r;
}
__device__ __forceinline__ uint32_t h2exp2u(uint32_t x) {
    uint32_t r;
    asm("ex2.approx.f16x2 %0, %1;" : "=r"(r) : "r"(x));
    return r;
}
__device__ __forceinline__ uint32_t packh2(float a, float b) {
    __half2 h = __floats2half2_rn(a, b);
    return *(uint32_t*)&h;
}

// D += A(16x16) * B(16x8), fp16 inputs, fp32 accum
__device__ __forceinline__ void mma16(float* c,
                                      uint32_t a0, uint32_t a1, uint32_t a2, uint32_t a3,
                                      uint32_t b0, uint32_t b1) {
    asm volatile("mma.sync.aligned.m16n8k16.row.col.f32.f16.f16.f32 "
                 "{%0,%1,%2,%3}, {%4,%5,%6,%7}, {%8,%9}, {%0,%1,%2,%3};"
                 : "+f"(c[0]), "+f"(c[1]), "+f"(c[2]), "+f"(c[3])
                 : "r"(a0), "r"(a1), "r"(a2), "r"(a3), "r"(b0), "r"(b1));
}
#define LDM_X4(d0,d1,d2,d3,a) \
    asm volatile("ldmatrix.sync.aligned.m8n8.x4.shared.b16 {%0,%1,%2,%3}, [%4];" \
                 : "=r"(d0), "=r"(d1), "=r"(d2), "=r"(d3) : "r"(a))
#define LDM_X4T(d0,d1,d2,d3,a) \
    asm volatile("ldmatrix.sync.aligned.m8n8.x4.trans.shared.b16 {%0,%1,%2,%3}, [%4];" \
                 : "=r"(d0), "=r"(d1), "=r"(d2), "=r"(d3) : "r"(a))

// log2(e) folded into q projection scale: scores land in exp2 domain.
#define QSCALE (0.125f * 1.44269504088896f)

// ---------------- depthwise 3x3 + BN, vertical multi-output columns ----------------
__global__ void __launch_bounds__(192) dw_all(const float* __restrict__ x,
    const float* __restrict__ qdw, const float* __restrict__ qsc,
    const float* __restrict__ qbi, const float* __restrict__ qmu,
    const float* __restrict__ qva,
    const float* __restrict__ kdw, const float* __restrict__ ksc,
    const float* __restrict__ kbi, const float* __restrict__ kmu,
    const float* __restrict__ kva,
    const float* __restrict__ vdw, const float* __restrict__ vsc,
    const float* __restrict__ vbi, const float* __restrict__ vmu,
    const float* __restrict__ vva)
{
    const int b = blockIdx.y;
    const int p = blockIdx.x * 4 + threadIdx.y;
    const int c = threadIdx.x * 4;
    const float* xb = x + (size_t)b * L_ * C_ + c;

    if (p < 784) {
        int y0 = (p / 56) * 4, xx = p % 56;
        float4 acc[4];
        #pragma unroll
        for (int i = 0; i < 4; i++) acc[i] = make_float4(0.f, 0.f, 0.f, 0.f);
        #pragma unroll
        for (int r = 0; r < 6; r++) {
            int iy = y0 - 1 + r;
            if ((unsigned)iy >= (unsigned)S_) continue;
            #pragma unroll
            for (int dx = 0; dx < 3; dx++) {
                int ix = xx + dx - 1;
                if ((unsigned)ix >= (unsigned)S_) continue;
                float4 xv = *(const float4*)&xb[(size_t)(iy * S_ + ix) * C_];
                #pragma unroll
                for (int i = 0; i < 4; i++) {
                    int dy = r - i;
                    if (dy < 0 || dy > 2) continue;
                    float4 wv = *(const float4*)&qdw[(dy * 3 + dx) * C_ + c];
                    acc[i].x += xv.x * wv.x; acc[i].y += xv.y * wv.y;
                    acc[i].z += xv.z * wv.z; acc[i].w += xv.w * wv.w;
                }
            }
        }
        float4 scv = *(const float4*)&qsc[c];
        float4 vav = *(const float4*)&qva[c];
        float4 muv = *(const float4*)&qmu[c];
        float4 biv = *(const float4*)&qbi[c];
        float a0 = scv.x * rsqrtf(vav.x + 1e-5f);
        float a1 = scv.y * rsqrtf(vav.y + 1e-5f);
        float a2 = scv.z * rsqrtf(vav.z + 1e-5f);
        float a3 = scv.w * rsqrtf(vav.w + 1e-5f);
        #pragma unroll
        for (int i = 0; i < 4; i++) {
            __half2* o = (__half2*)&g_hq[((size_t)b * L_ + (y0 + i) * S_ + xx) * C_ + c];
            o[0] = __floats2half2_rn((acc[i].x - muv.x) * a0 + biv.x,
                                     (acc[i].y - muv.y) * a1 + biv.y);
            o[1] = __floats2half2_rn((acc[i].z - muv.z) * a2 + biv.z,
                                     (acc[i].w - muv.w) * a3 + biv.w);
        }
    } else {
        int p2 = p - 784;
        int y0 = (p2 / SO_) * 2, xx = p2 % SO_;
        float4 ka[2], va[2];
        #pragma unroll
        for (int i = 0; i < 2; i++) {
            ka[i] = make_float4(0.f, 0.f, 0.f, 0.f);
            va[i] = make_float4(0.f, 0.f, 0.f, 0.f);
        }
        #pragma unroll
        for (int r = 0; r < 5; r++) {
            int iy = 2 * y0 + r;
            if (iy >= S_) continue;
            #pragma unroll
            for (int dx = 0; dx < 3; dx++) {
                int ix = 2 * xx + dx;
                if (ix >= S_) continue;
                float4 xv = *(const float4*)&xb[(size_t)(iy * S_ + ix) * C_];
                #pragma unroll
                for (int i = 0; i < 2; i++) {
                    int dy = r - 2 * i;
                    if (dy < 0 || dy > 2) continue;
                    float4 wk = *(const float4*)&kdw[(dy * 3 + dx) * C_ + c];
                    float4 wv = *(const float4*)&vdw[(dy * 3 + dx) * C_ + c];
                    ka[i].x += xv.x * wk.x; ka[i].y += xv.y * wk.y;
                    ka[i].z += xv.z * wk.z; ka[i].w += xv.w * wk.w;
                    va[i].x += xv.x * wv.x; va[i].y += xv.y * wv.y;
                    va[i].z += xv.z * wv.z; va[i].w += xv.w * wv.w;
                }
            }
        }
        {
            float4 scv = *(const float4*)&ksc[c];
            float4 vav = *(const float4*)&kva[c];
            float4 muv = *(const float4*)&kmu[c];
            float4 biv = *(const float4*)&kbi[c];
            float a0 = scv.x * rsqrtf(vav.x + 1e-5f);
            float a1 = scv.y * rsqrtf(vav.y + 1e-5f);
            float a2 = scv.z * rsqrtf(vav.z + 1e-5f);
            float a3 = scv.w * rsqrtf(vav.w + 1e-5f);
            #pragma unroll
            for (int i = 0; i < 2; i++) {
                __half2* o = (__half2*)&g_hk[((size_t)b * L2_ + (y0 + i) * SO_ + xx) * C_ + c];
                o[0] = __floats2half2_rn((ka[i].x - muv.x) * a0 + biv.x,
                                         (ka[i].y - muv.y) * a1 + biv.y);
                o[1] = __floats2half2_rn((ka[i].z - muv.z) * a2 + biv.z,
                                         (ka[i].w - muv.w) * a3 + biv.w);
            }
        }
        {
            float4 scv = *(const float4*)&vsc[c];
            float4 vav = *(const float4*)&vva[c];
            float4 muv = *(const float4*)&vmu[c];
            float4 biv = *(const float4*)&vbi[c];
            float a0 = scv.x * rsqrtf(vav.x + 1e-5f);
            float a1 = scv.y * rsqrtf(vav.y + 1e-5f);
            float a2 = scv.z * rsqrtf(vav.z + 1e-5f);
            float a3 = scv.w * rsqrtf(vav.w + 1e-5f);
            #pragma unroll
            for (int i = 0; i < 2; i++) {
                __half2* o = (__half2*)&g_hv[((size_t)b * L2_ + (y0 + i) * SO_ + xx) * C_ + c];
                o[0] = __floats2half2_rn((va[i].x - muv.x) * a0 + biv.x,
                                         (va[i].y - muv.y) * a1 + biv.y);
                o[1] = __floats2half2_rn((va[i].z - muv.z) * a2 + biv.z,
                                         (va[i].w - muv.w) * a3 + biv.w);
            }
        }
    }
}

// ---------------- pointwise 1x1 conv: whole-tile staging, single barrier ----------------
#define PW_SMEM (128*200*2 + 192*72*2)
__global__ void __launch_bounds__(256) pw_all(const float* __restrict__ Wq,
                                              const float* __restrict__ Wk,
                                              const float* __restrict__ Wv)
{
    const __half* A; const float* W; __half* Cp; float oscale; int m0;
    int bx = blockIdx.x;
    if (bx < 196)      { A = g_hq; Cp = g_q; W = Wq; oscale = QSCALE; m0 = bx * 128; }
    else if (bx < 245) { A = g_hk; Cp = g_k; W = Wk; oscale = 1.0f;  m0 = (bx - 196) * 128; }
    else               { A = g_hv; Cp = g_v; W = Wv; oscale = 1.0f;  m0 = (bx - 245) * 128; }
    const int n0 = blockIdx.y * 64;

    extern __shared__ char smc[];
    __half* As = (__half*)smc;
    __half* Bs = (__half*)(smc + 128 * 200 * 2);

    const int tid = threadIdx.x;
    const int w = tid >> 5, lane = tid & 31;
    const int g = lane >> 2, tg = lane & 3;
    const int lm = lane >> 3, lr = lane & 7;
    const uint32_t sAs = smem_u32(As), sBs = smem_u32(Bs);

    #pragma unroll
    for (int i = 0; i < 12; i++) {
        int idx = tid + i * 256;
        int r = idx / 24, ch = idx % 24;
        cp16(&As[r * 200 + ch * 8], A + (size_t)(m0 + r) * C_ + ch * 8);
    }
    CP_COMMIT();

    #pragma unroll
    for (int i = 0; i < 12; i++) {
        int idx = tid + i * 256;
        int k = idx >> 4, nq = idx & 15;
        float4 wv = *(const float4*)&W[(size_t)k * C_ + n0 + nq * 4];
        __half2 h01 = __floats2half2_rn(wv.x, wv.y);
        __half2 h23 = __floats2half2_rn(wv.z, wv.w);
        uint2 u; u.x = *(uint32_t*)&h01; u.y = *(uint32_t*)&h23;
        *(uint2*)&Bs[k * 72 + nq * 4] = u;
    }
    CP_WAIT0();
    __syncthreads();

    float Cv[8][4];
    #pragma unroll
    for (int i = 0; i < 8; i++)
        #pragma unroll
        for (int j = 0; j < 4; j++) Cv[i][j] = 0.f;

    const uint32_t aBase = sAs + (uint32_t)(((w * 16 + (lm & 1) * 8 + lr) * 200
                                             + (lm >> 1) * 8) * 2);
    const uint32_t bRow  = (uint32_t)(((lm & 1) * 8 + lr) * 72) * 2;
    #pragma unroll
    for (int ks = 0; ks < 12; ks++) {
        uint32_t a0, a1, a2, a3;
        LDM_X4(a0, a1, a2, a3, aBase + ks * 32);
        #pragma unroll
        for (int nfp = 0; nfp < 4; nfp++) {
            uint32_t b00, b01, b10, b11;
            uint32_t ba = sBs + (uint32_t)(ks * 16 * 72 * 2) + bRow
                        + (uint32_t)(((nfp * 2 + (lm >> 1)) * 8) * 2);
            LDM_X4T(b00, b01, b10, b11, ba);
            mma16(Cv[nfp * 2],     a0, a1, a2, a3, b00, b01);
            mma16(Cv[nfp * 2 + 1], a0, a1, a2, a3, b10, b11);
        }
    }

    const int r0 = 16 * w + g;
    __half* o0 = Cp + (size_t)(m0 + r0) * C_ + n0;
    __half* o1 = o0 + (size_t)8 * C_;
    #pragma unroll
    for (int nf = 0; nf < 8; nf++) {
        *(__half2*)&o0[nf * 8 + 2 * tg] =
            __floats2half2_rn(Cv[nf][0] * oscale, Cv[nf][1] * oscale);
        *(__half2*)&o1[nf * 8 + 2 * tg] =
            __floats2half2_rn(Cv[nf][2] * oscale, Cv[nf][3] * oscale);
    }
}

// ---------------- flash attention: register-direct P, mma row-sums, f16x2 exp ----------------
#define NKT 13
#define ATTN_SMEM ((128*72 + 4*64*72) * 2)
__global__ void __launch_bounds__(256, 2) attn_mma(float* __restrict__ out)
{
    extern __shared__ char smc[];
    __half* Qs = (__half*)smc;
    __half* Ks = Qs + 128 * 72;
    __half* Vs = Ks + 2 * 64 * 72;

    const int tid = threadIdx.x;
    const int w = tid >> 5, lane = tid & 31;
    const int g = lane >> 2, tg = lane & 3;
    const int lm = lane >> 3, lr = lane & 7;
    const int q0 = blockIdx.x * 128;
    const int h = blockIdx.y, b = blockIdx.z;

    const __half* qp = g_q + (size_t)b * L_ * C_ + h * D_;
    const __half* kp = g_k + (size_t)b * L2_ * C_ + h * D_;
    const __half* vp = g_v + (size_t)b * L2_ * C_ + h * D_;

    // prologue: Q (group 0)
    #pragma unroll
    for (int p = 0; p < 4; p++) {
        int id = tid + p * 256;
        int r = id >> 3, off = (id & 7) * 8;
        int rg = q0 + r; if (rg > L_ - 1) rg = L_ - 1;
        cp16(&Qs[r * 72 + off], qp + (size_t)rg * C_ + off);
    }
    CP_COMMIT();
    // K+V tile 0 (group 1)
    #pragma unroll
    for (int p = 0; p < 2; p++) {
        int id = tid + p * 256;
        int j = id >> 3, off = (id & 7) * 8;
        cp16(&Ks[j * 72 + off], kp + (size_t)j * C_ + off);
        cp16(&Vs[j * 72 + off], vp + (size_t)j * C_ + off);
    }
    CP_COMMIT();
    CP_WAIT1();          // Q done
    __syncthreads();

    // Q fragments via ldmatrix (16 rows x 64 cols per warp)
    uint32_t Qa[4][4];
    {
        uint32_t base = smem_u32(Qs) + (uint32_t)(((w * 16 + (lm & 1) * 8 + lr) * 72
                                                   + (lm >> 1) * 8) * 2);
        #pragma unroll
        for (int ks = 0; ks < 4; ks++)
            LDM_X4(Qa[ks][0], Qa[ks][1], Qa[ks][2], Qa[ks][3], base + ks * 32);
    }

    float Ov[8][4];
    #pragma unroll
    for (int i = 0; i < 8; i++)
        #pragma unroll
        for (int j = 0; j < 4; j++) Ov[i][j] = 0.f;
    float Lv[4] = {0.f, 0.f, 0.f, 0.f};
    float m0 = -1e30f, m1 = -1e30f;

    const uint32_t ONES = 0x3C003C00u;   // half2(1,1)
    // ldmatrix row offsets
    const uint32_t bRowK = (uint32_t)(((lm >> 1) * 8 + lr) * 72 * 2);  // QK: j rows
    const uint32_t bRowV = (uint32_t)(((lm & 1) * 8 + lr) * 72 * 2);   // PV: k(j) rows, trans

    for (int kt = 0; kt < NKT; kt++) {
        CP_WAIT0();                      // K/V tile kt arrived
        __syncthreads();                 // all warps done with the other buffer

        if (kt + 1 < NKT) {              // prefetch K/V (kt+1)
            int nb = (kt + 1) & 1;
            int j0n = (kt + 1) * 64;
            __half* Kb = Ks + nb * (64 * 72);
            __half* Vb = Vs + nb * (64 * 72);
            #pragma unroll
            for (int p = 0; p < 2; p++) {
                int id = tid + p * 256;
                int j = id >> 3, off = (id & 7) * 8;
                int jg = j0n + j; if (jg > L2_ - 1) jg = L2_ - 1;
                cp16(&Kb[j * 72 + off], kp + (size_t)jg * C_ + off);
                cp16(&Vb[j * 72 + off], vp + (size_t)jg * C_ + off);
            }
            CP_COMMIT();
        }

        const uint32_t sK = smem_u32(Ks + (kt & 1) * (64 * 72));
        const uint32_t sV = smem_u32(Vs + (kt & 1) * (64 * 72));

        // S = Q K^T : warp 16 x 64
        float Sc[8][4];
        #pragma unroll
        for (int i = 0; i < 8; i++)
            #pragma unroll
            for (int j = 0; j < 4; j++) Sc[i][j] = 0.f;
        #pragma unroll
        for (int ks = 0; ks < 4; ks++) {
            #pragma unroll
            for (int nfp = 0; nfp < 4; nfp++) {
                uint32_t b00, b01, b10, b11;
                uint32_t ba = sK + (uint32_t)(nfp * 16 * 72 * 2) + bRowK
                            + (uint32_t)((ks * 16 + (lm & 1) * 8) * 2);
                LDM_X4(b00, b01, b10, b11, ba);
                mma16(Sc[nfp * 2],     Qa[ks][0], Qa[ks][1], Qa[ks][2], Qa[ks][3], b00, b01);
                mma16(Sc[nfp * 2 + 1], Qa[ks][0], Qa[ks][1], Qa[ks][2], Qa[ks][3], b10, b11);
            }
        }

        int j0 = kt * 64;
        if (j0 + 64 > L2_) {             // mask invalid keys (last tile)
            #pragma unroll
            for (int nf = 0; nf < 8; nf++) {
                int c0 = j0 + nf * 8 + 2 * tg;
                if (c0 >= L2_)     { Sc[nf][0] = -1e4f; Sc[nf][2] = -1e4f; }
                if (c0 + 1 >= L2_) { Sc[nf][1] = -1e4f; Sc[nf][3] = -1e4f; }
            }
        }

        // online softmax, exp2 domain (rows g / g+8; quad reduce xor 1,2)
        float mx0 = -1e30f, mx1 = -1e30f;
        #pragma unroll
        for (int nf = 0; nf < 8; nf++) {
            mx0 = fmaxf(mx0, fmaxf(Sc[nf][0], Sc[nf][1]));
            mx1 = fmaxf(mx1, fmaxf(Sc[nf][2], Sc[nf][3]));
        }
        mx0 = fmaxf(mx0, __shfl_xor_sync(0xffffffffu, mx0, 1));
        mx0 = fmaxf(mx0, __shfl_xor_sync(0xffffffffu, mx0, 2));
        mx1 = fmaxf(mx1, __shfl_xor_sync(0xffffffffu, mx1, 1));
        mx1 = fmaxf(mx1, __shfl_xor_sync(0xffffffffu, mx1, 2));
        float mn0 = fmaxf(m0, mx0), mn1 = fmaxf(m1, mx1);
        float al0 = ex2(m0 - mn0), al1 = ex2(m1 - mn1);
        m0 = mn0; m1 = mn1;

        // rescale accumulators
        #pragma unroll
        for (int df = 0; df < 8; df++) {
            Ov[df][0] *= al0; Ov[df][1] *= al0;
            Ov[df][2] *= al1; Ov[df][3] *= al1;
        }
        Lv[0] *= al0; Lv[1] *= al0; Lv[2] *= al1; Lv[3] *= al1;

        // P = exp2(S - m) in half2 registers (C-frag == A-frag layout)
        uint32_t Pa[8][2];
        #pragma unroll
        for (int nf = 0; nf < 8; nf++) {
            Pa[nf][0] = h2exp2u(packh2(Sc[nf][0] - mn0, Sc[nf][1] - mn0)); // row g
            Pa[nf][1] = h2exp2u(packh2(Sc[nf][2] - mn1, Sc[nf][3] - mn1)); // row g+8
        }

        // O += P V ; l += P 1   (A = P regs, B = V via ldmatrix.trans)
        #pragma unroll
        for (int ks = 0; ks < 4; ks++) {
            uint32_t a0 = Pa[2 * ks][0],     a1 = Pa[2 * ks][1];
            uint32_t a2 = Pa[2 * ks + 1][0], a3 = Pa[2 * ks + 1][1];
            #pragma unroll
            for (int dfp = 0; dfp < 4; dfp++) {
                uint32_t b00, b01, b10, b11;
                uint32_t ba = sV + (uint32_t)(ks * 16 * 72 * 2) + bRowV
                            + (uint32_t)(((dfp * 2 + (lm >> 1)) * 8) * 2);
                LDM_X4T(b00, b01, b10, b11, ba);
                mma16(Ov[dfp * 2],     a0, a1, a2, a3, b00, b01);
                mma16(Ov[dfp * 2 + 1], a0, a1, a2, a3, b10, b11);
            }
            mma16(Lv, a0, a1, a2, a3, ONES, ONES);
        }
    }

    // epilogue (fp32 output); every Lv column equals the row sum
    float i0 = 1.f / Lv[0], i1 = 1.f / Lv[2];
    int rg0 = q0 + 16 * w + g;
    if (rg0 < L_) {
        float* o = out + ((size_t)b * L_ + rg0) * C_ + h * D_;
        #pragma unroll
        for (int df = 0; df < 8; df++)
            *(float2*)&o[df * 8 + 2 * tg] =
                make_float2(Ov[df][0] * i0, Ov[df][1] * i0);
    }
    int rg1 = rg0 + 8;
    if (rg1 < L_) {
        float* o = out + ((size_t)b * L_ + rg1) * C_ + h * D_;
        #pragma unroll
        for (int df = 0; df < 8; df++)
            *(float2*)&o[df * 8 + 2 * tg] =
                make_float2(Ov[df][2] * i1, Ov[df][3] * i1);
    }
}

// ---------------- launch ----------------
extern "C" void kernel_launch(void* const* d_in, const int* in_sizes, int n_in,
                              void* d_out, int out_size)
{
    const float* x       = (const float*)d_in[0];
    const float* q_dw    = (const float*)d_in[1];
    const float* q_scale = (const float*)d_in[2];
    const float* q_bias  = (const float*)d_in[3];
    const float* q_mean  = (const float*)d_in[4];
    const float* q_var   = (const float*)d_in[5];
    const float* q_pw    = (const float*)d_in[6];
    const float* k_dw    = (const float*)d_in[7];
    const float* k_scale = (const float*)d_in[8];
    const float* k_bias  = (const float*)d_in[9];
    const float* k_mean  = (const float*)d_in[10];
    const float* k_var   = (const float*)d_in[11];
    const float* k_pw    = (const float*)d_in[12];
    const float* v_dw    = (const float*)d_in[13];
    const float* v_scale = (const float*)d_in[14];
    const float* v_bias  = (const float*)d_in[15];
    const float* v_mean  = (const float*)d_in[16];
    const float* v_var   = (const float*)d_in[17];
    const float* v_pw    = (const float*)d_in[18];
    float* out = (float*)d_out;

    cudaFuncSetAttribute(pw_all,
                         cudaFuncAttributeMaxDynamicSharedMemorySize, PW_SMEM);
    cudaFuncSetAttribute(attn_mma,
                         cudaFuncAttributeMaxDynamicSharedMemorySize, ATTN_SMEM);

    dw_all<<<dim3(294, B_), dim3(48, 4)>>>(x,
        q_dw, q_scale, q_bias, q_mean, q_var,
        k_dw, k_scale, k_bias, k_mean, k_var,
        v_dw, v_scale, v_bias, v_mean, v_var);

    pw_all<<<dim3(294, 3), 256, PW_SMEM>>>(q_pw, k_pw, v_pw);

    attn_mma<<<dim3((L_ + 127) / 128, H_, B_), 256, ATTN_SMEM>>>(out);
}